// round 11
// baseline (speedup 1.0000x reference)
#include <cuda_runtime.h>
#include <cuda_bf16.h>
#include <cstdint>
#include <cstddef>

// Problem constants
#define B_   4
#define C_   384
#define S_   4096

typedef __nv_bfloat16 bf16;

// ---------------------------------------------------------------------------
// Scratch (device globals; no allocation allowed in kernel_launch)
// ---------------------------------------------------------------------------
__device__ float g_scl[B_ * S_];                          // per-pixel rms scale
__device__ bf16  g_wg [3 * C_ * C_];                      // bf16(w_qkv * gamma)
__device__ bf16  g_wp [C_ * C_];                          // bf16(w_proj)
__device__ bf16  g_xnt[(size_t)B_ * S_ * C_];             // [b][s][c] normed x
__device__ bf16  g_qkt[(size_t)B_ * S_ * 2 * C_];         // [b][s][q|k]
__device__ bf16  g_v  [(size_t)B_ * C_ * S_];             // [b][c][s]
__device__ bf16  g_P  [(size_t)B_ * S_ * S_];             // [b][i][j]
__device__ bf16  g_Ot [(size_t)B_ * S_ * C_];             // [b][s][c]

// ---------------------------------------------------------------------------
// PTX helpers (baseline ISA only)
// ---------------------------------------------------------------------------
#define CP_ASYNC16(dst, src) \
    asm volatile("cp.async.cg.shared.global [%0], [%1], 16;" :: "r"(dst), "l"(src))
#define CP_COMMIT() asm volatile("cp.async.commit_group;" ::: "memory")
#define CP_WAIT(n)  asm volatile("cp.async.wait_group %0;" :: "n"(n) : "memory")

__device__ __forceinline__ void ldsm4(uint32_t& r0, uint32_t& r1, uint32_t& r2,
                                      uint32_t& r3, uint32_t addr) {
    asm volatile("ldmatrix.sync.aligned.m8n8.x4.shared.b16 {%0,%1,%2,%3}, [%4];"
                 : "=r"(r0), "=r"(r1), "=r"(r2), "=r"(r3) : "r"(addr));
}

__device__ __forceinline__ void mma16(float* c, const uint32_t* a, const uint32_t* b) {
    asm volatile(
        "mma.sync.aligned.m16n8k16.row.col.f32.bf16.bf16.f32 "
        "{%0,%1,%2,%3}, {%4,%5,%6,%7}, {%8,%9}, {%0,%1,%2,%3};"
        : "+f"(c[0]), "+f"(c[1]), "+f"(c[2]), "+f"(c[3])
        : "r"(a[0]), "r"(a[1]), "r"(a[2]), "r"(a[3]), "r"(b[0]), "r"(b[1]));
}

// ---------------------------------------------------------------------------
// Prep kernels
// ---------------------------------------------------------------------------
__global__ void wg_kernel(bf16* __restrict__ wg, const float* __restrict__ w,
                          const float* __restrict__ g) {
    int i = blockIdx.x * 256 + threadIdx.x;
    if (i < 3 * C_ * C_) wg[i] = __float2bfloat16_rn(w[i] * g[i % C_]);
}

__global__ void wp_kernel(bf16* __restrict__ wp, const float* __restrict__ w) {
    int i = blockIdx.x * 256 + threadIdx.x;
    if (i < C_ * C_) wp[i] = __float2bfloat16_rn(w[i]);
}

__global__ void scale_kernel(float* __restrict__ scl, const float* __restrict__ x) {
    int s = blockIdx.x * 256 + threadIdx.x;
    int b = blockIdx.y;
    const float* xb = x + (size_t)b * C_ * S_ + s;
    float acc = 0.f;
#pragma unroll 8
    for (int c = 0; c < C_; ++c) {
        float v = xb[(size_t)c * S_];
        acc += v * v;
    }
    float l2 = sqrtf(acc);
    scl[b * S_ + s] = 19.595917942265423f / fmaxf(l2, 1e-12f);  // sqrt(384)/max(l2,eps)
}

// transpose + scale: xnt[b][s][c] = bf16(x[b][c][s] * scl[b][s])
__global__ void xnt_kernel(bf16* __restrict__ xnt, const float* __restrict__ x,
                           const float* __restrict__ scl) {
    __shared__ float t[32][33];
    int b = blockIdx.z;
    int s0 = blockIdx.x * 32, c0 = blockIdx.y * 32;
    int tx = threadIdx.x, ty = threadIdx.y;   // 32 x 8
    const float* xb = x + (size_t)b * C_ * S_;
#pragma unroll
    for (int i = 0; i < 4; ++i)
        t[ty + i * 8][tx] = xb[(size_t)(c0 + ty + i * 8) * S_ + s0 + tx];
    __syncthreads();
    bf16* o = xnt + (size_t)b * S_ * C_;
#pragma unroll
    for (int i = 0; i < 4; ++i) {
        int s = s0 + ty + i * 8;
        o[(size_t)s * C_ + c0 + tx] =
            __float2bfloat16_rn(t[tx][ty + i * 8] * scl[b * S_ + s]);
    }
}

// ---------------------------------------------------------------------------
// Warp-MMA bf16 GEMM: D[m][n] = sum_k A[m][k]*B[n][k]
// 128x128 block tile, 4 warps (2M x 2N, warp tile 64x64), Kc=32 (2 k16 steps),
// 4-stage cp.async pipeline, ldmatrix operand fetch, fp32 accumulate.
// Warp tile 64x64 cuts smem fragment traffic to 128B/MMA (crossbar relief).
//   EPI 0: +e2[n]  -> bf16   (qk bias)
//   EPI 1: +e2[m]  -> bf16   (v bias)
//   EPI 2: *1/sqrt(C) -> bf16 (scores)
//   EPI 3: plain   -> bf16   (AV -> Ot)
//   EPI 4: +e2[m] + e3[m*ldc+n] -> fp32 (proj bias + residual)
// All M,N multiples of 128; K multiple of 32.
// ---------------------------------------------------------------------------
#define SRB    80                    // bytes per smem row (64 data + 16 pad)
#define ATILEB (128 * SRB)           // 10240 B per operand tile
#define STGB   (2 * ATILEB)          // 20480 B per stage
#define NSTG   4

template <int EPI>
__global__ __launch_bounds__(128)
void mma_gemm(const bf16* __restrict__ Ag, const bf16* __restrict__ Bg,
              void* __restrict__ Cgv, int K, int lda, int ldb, int ldc,
              size_t sA, size_t sB, size_t sC,
              const float* __restrict__ e2, const float* __restrict__ e3,
              size_t e3s)
{
    extern __shared__ __align__(16) char smem[];   // NSTG * STGB bytes

    const int tid  = threadIdx.x;                  // 0..127
    const int lane = tid & 31, wid = tid >> 5;     // 4 warps
    const int warpM = wid & 1, warpN = wid >> 1;   // 2x2 layout of 64x64 tiles
    const int bz = blockIdx.z;
    const int m0 = blockIdx.y * 128, n0 = blockIdx.x * 128;

    const bf16* A  = Ag + (size_t)bz * sA + (size_t)m0 * lda;
    const bf16* Bp = Bg + (size_t)bz * sB + (size_t)n0 * ldb;
    const uint32_t smB = (uint32_t)__cvta_generic_to_shared(smem);

    // global->smem loader: thread covers rows lr+{0,32,64,96}, 16B at k-halfs lq
    const int lr = tid >> 2;                         // 0..31
    const int lq = (tid & 3) * 8;                    // halfs
    const uint32_t lqB = (uint32_t)(tid & 3) * 16;   // bytes

    // ldmatrix per-thread source offsets (bytes within a stage)
    const int g = lane >> 3, r = lane & 7;
    const uint32_t aOff = (uint32_t)((warpM * 64 + (g & 1) * 8 + r) * SRB + (g >> 1) * 16);
    const uint32_t bOff = (uint32_t)(ATILEB + (warpN * 64 + (g & 1) * 8 + r) * SRB + (g >> 1) * 16);

    float acc[4][8][4];
#pragma unroll
    for (int mf = 0; mf < 4; ++mf)
#pragma unroll
        for (int nf = 0; nf < 8; ++nf)
#pragma unroll
            for (int i = 0; i < 4; ++i) acc[mf][nf][i] = 0.f;

    const int nK = K >> 5;   // Kc = 32

    auto LOAD = [&](int s) {
        const int p = s & (NSTG - 1);
        const bf16* As = A  + (size_t)lr * lda + s * 32 + lq;
        const bf16* Bs = Bp + (size_t)lr * ldb + s * 32 + lq;
        uint32_t dA = smB + (uint32_t)(p * STGB + lr * SRB) + lqB;
        uint32_t dB = dA + (uint32_t)ATILEB;
#pragma unroll
        for (int rr = 0; rr < 4; ++rr) {
            CP_ASYNC16(dA + rr * 32 * SRB, As + (size_t)(rr * 32) * lda);
            CP_ASYNC16(dB + rr * 32 * SRB, Bs + (size_t)(rr * 32) * ldb);
        }
    };

    LOAD(0); CP_COMMIT();
    LOAD(1); CP_COMMIT();
    LOAD(2); CP_COMMIT();

    for (int s = 0; s < nK; ++s) {
        CP_WAIT(2);              // stage s landed
        __syncthreads();         // visibility + buffer-reuse fence
        if (s + 3 < nK) LOAD(s + 3);
        CP_COMMIT();             // empty group at tail keeps counts uniform

        const uint32_t pb = smB + (uint32_t)((s & (NSTG - 1)) * STGB);
#pragma unroll
        for (int kk = 0; kk < 2; ++kk) {      // two k16 steps per stage
            uint32_t afr[4][4], bfr[8][2];
#pragma unroll
            for (int mf = 0; mf < 4; ++mf)
                ldsm4(afr[mf][0], afr[mf][1], afr[mf][2], afr[mf][3],
                      pb + aOff + (uint32_t)(mf * 16 * SRB + kk * 32));
#pragma unroll
            for (int pr = 0; pr < 4; ++pr)
                ldsm4(bfr[2 * pr][0], bfr[2 * pr + 1][0],
                      bfr[2 * pr][1], bfr[2 * pr + 1][1],
                      pb + bOff + (uint32_t)(pr * 16 * SRB + kk * 32));
#pragma unroll
            for (int mf = 0; mf < 4; ++mf)
#pragma unroll
                for (int nf = 0; nf < 8; ++nf)
                    mma16(acc[mf][nf], afr[mf], bfr[nf]);
        }
    }

    // ---- epilogue ----
    const int rBase = m0 + warpM * 64 + (lane >> 2);
    const int cBase = n0 + warpN * 64 + (lane & 3) * 2;
#pragma unroll
    for (int mf = 0; mf < 4; ++mf) {
#pragma unroll
        for (int h = 0; h < 2; ++h) {
            const int row = rBase + mf * 16 + h * 8;
            float bm = 0.f;
            if (EPI == 1 || EPI == 4) bm = e2[row];
#pragma unroll
            for (int nf = 0; nf < 8; ++nf) {
                const int col = cBase + nf * 8;
                float u0 = acc[mf][nf][2 * h];
                float u1 = acc[mf][nf][2 * h + 1];
                float2 o;
                if (EPI == 0) {
                    float2 bn = *(const float2*)(e2 + col);
                    o.x = u0 + bn.x; o.y = u1 + bn.y;
                } else if (EPI == 1) {
                    o.x = u0 + bm; o.y = u1 + bm;
                } else if (EPI == 2) {
                    const float sc = 0.05103103630798288f;   // 1/sqrt(384)
                    o.x = u0 * sc; o.y = u1 * sc;
                } else if (EPI == 3) {
                    o.x = u0; o.y = u1;
                } else {
                    const float* e3row = e3 + (size_t)bz * e3s + (size_t)row * ldc;
                    float2 rx = *(const float2*)(e3row + col);
                    o.x = u0 + bm + rx.x; o.y = u1 + bm + rx.y;
                }
                if (EPI == 4) {
                    float* Crow = (float*)Cgv + (size_t)bz * sC + (size_t)row * ldc;
                    *(float2*)(Crow + col) = o;
                } else {
                    bf16* Crow = (bf16*)Cgv + (size_t)bz * sC + (size_t)row * ldc;
                    __nv_bfloat162 hv = __floats2bfloat162_rn(o.x, o.y);
                    *(__nv_bfloat162*)(Crow + col) = hv;
                }
            }
        }
    }
}

// ---------------------------------------------------------------------------
// Row softmax over 4096 bf16 columns, one block (256 thr) per row.
// ---------------------------------------------------------------------------
__global__ void softmax_kernel(bf16* __restrict__ P) {
    uint4* p = reinterpret_cast<uint4*>(P + (size_t)blockIdx.x * S_);
    const int t = threadIdx.x;

    uint4 u[2] = { p[t], p[t + 256] };
    float f[16];
#pragma unroll
    for (int i = 0; i < 2; ++i) {
        const uint32_t* w = (const uint32_t*)&u[i];
#pragma unroll
        for (int j = 0; j < 4; ++j) {
            float2 d = __bfloat1622float2(*(const __nv_bfloat162*)&w[j]);
            f[i * 8 + 2 * j] = d.x;
            f[i * 8 + 2 * j + 1] = d.y;
        }
    }

    float mx = -3.4e38f;
#pragma unroll
    for (int i = 0; i < 16; ++i) mx = fmaxf(mx, f[i]);

    __shared__ float redMax[8];
    __shared__ float redSum[8];
#pragma unroll
    for (int o = 16; o > 0; o >>= 1)
        mx = fmaxf(mx, __shfl_xor_sync(0xffffffffu, mx, o));
    if ((t & 31) == 0) redMax[t >> 5] = mx;
    __syncthreads();
    mx = redMax[0];
#pragma unroll
    for (int w = 1; w < 8; ++w) mx = fmaxf(mx, redMax[w]);

    float sum = 0.f;
#pragma unroll
    for (int i = 0; i < 16; ++i) {
        f[i] = __expf(f[i] - mx);
        sum += f[i];
    }
#pragma unroll
    for (int o = 16; o > 0; o >>= 1)
        sum += __shfl_xor_sync(0xffffffffu, sum, o);
    if ((t & 31) == 0) redSum[t >> 5] = sum;
    __syncthreads();
    sum = (redSum[0] + redSum[1]) + (redSum[2] + redSum[3]) +
          (redSum[4] + redSum[5]) + (redSum[6] + redSum[7]);
    float inv = 1.f / sum;

#pragma unroll
    for (int i = 0; i < 2; ++i) {
        uint32_t* w = (uint32_t*)&u[i];
#pragma unroll
        for (int j = 0; j < 4; ++j) {
            __nv_bfloat162 hv = __floats2bfloat162_rn(f[i * 8 + 2 * j] * inv,
                                                      f[i * 8 + 2 * j + 1] * inv);
            w[j] = *(const uint32_t*)&hv;
        }
    }
    p[t] = u[0];
    p[t + 256] = u[1];
}

// ---------------------------------------------------------------------------
// Launch
// ---------------------------------------------------------------------------
extern "C" void kernel_launch(void* const* d_in, const int* in_sizes, int n_in,
                              void* d_out, int out_size) {
    const float* x      = (const float*)d_in[0];   // [4,384,64,64]
    const float* gamma  = (const float*)d_in[1];   // [384]
    const float* w_qkv  = (const float*)d_in[2];   // [1152,384]
    const float* b_qkv  = (const float*)d_in[3];   // [1152]
    const float* w_proj = (const float*)d_in[4];   // [384,384]
    const float* b_proj = (const float*)d_in[5];   // [384]
    float* out = (float*)d_out;                    // [4,384,64,64]

    float *scl;
    bf16 *wg, *wp, *xnt, *qkt, *v, *P, *Ot;
    cudaGetSymbolAddress((void**)&scl, g_scl);
    cudaGetSymbolAddress((void**)&wg,  g_wg);
    cudaGetSymbolAddress((void**)&wp,  g_wp);
    cudaGetSymbolAddress((void**)&xnt, g_xnt);
    cudaGetSymbolAddress((void**)&qkt, g_qkt);
    cudaGetSymbolAddress((void**)&v,   g_v);
    cudaGetSymbolAddress((void**)&P,   g_P);
    cudaGetSymbolAddress((void**)&Ot,  g_Ot);

    const int SMEM_DYN = NSTG * STGB;   // 81920 bytes
    cudaFuncSetAttribute((const void*)mma_gemm<0>, cudaFuncAttributeMaxDynamicSharedMemorySize, SMEM_DYN);
    cudaFuncSetAttribute((const void*)mma_gemm<1>, cudaFuncAttributeMaxDynamicSharedMemorySize, SMEM_DYN);
    cudaFuncSetAttribute((const void*)mma_gemm<2>, cudaFuncAttributeMaxDynamicSharedMemorySize, SMEM_DYN);
    cudaFuncSetAttribute((const void*)mma_gemm<3>, cudaFuncAttributeMaxDynamicSharedMemorySize, SMEM_DYN);
    cudaFuncSetAttribute((const void*)mma_gemm<4>, cudaFuncAttributeMaxDynamicSharedMemorySize, SMEM_DYN);

    // 1) fold gamma into w_qkv (bf16); convert w_proj (bf16)
    wg_kernel<<<(3 * C_ * C_ + 255) / 256, 256>>>(wg, w_qkv, gamma);
    wp_kernel<<<(C_ * C_ + 255) / 256, 256>>>(wp, w_proj);
    // 2) per-pixel rms scale
    scale_kernel<<<dim3(S_ / 256, B_), 256>>>(scl, x);
    // 3) xnt[b][s][c] = bf16(x[b][c][s] * scl)
    xnt_kernel<<<dim3(S_ / 32, C_ / 32, B_), dim3(32, 8)>>>(xnt, x, scl);
    // 4) qk_t[b][s][o] = xnt @ wg[0:768]^T + b_qkv[o]      M=4096 N=768 K=384
    mma_gemm<0><<<dim3(6, 32, B_), 128, SMEM_DYN>>>(
        xnt, wg, qkt, C_, C_, C_, 2 * C_,
        (size_t)S_ * C_, 0, (size_t)S_ * 2 * C_, b_qkv, nullptr, 0);
    // 5) v[b][c][s] = wg[768:] @ xnt^T + b_qkv[768+c]      M=384 N=4096 K=384
    mma_gemm<1><<<dim3(32, 3, B_), 128, SMEM_DYN>>>(
        wg + (size_t)2 * C_ * C_, xnt, v, C_, C_, C_, S_,
        0, (size_t)S_ * C_, (size_t)C_ * S_, b_qkv + 2 * C_, nullptr, 0);
    // 6) P[b][i][j] = q_i . k_j / sqrt(C)                  M=N=4096 K=384
    mma_gemm<2><<<dim3(32, 32, B_), 128, SMEM_DYN>>>(
        qkt, qkt + C_, P, C_, 2 * C_, 2 * C_, S_,
        (size_t)S_ * 2 * C_, (size_t)S_ * 2 * C_, (size_t)S_ * S_, nullptr, nullptr, 0);
    // 7) softmax rows
    softmax_kernel<<<B_ * S_, 256>>>(P);
    // 8) Ot[b][i][c] = P @ v^T                             M=4096 N=384 K=4096
    mma_gemm<3><<<dim3(3, 32, B_), 128, SMEM_DYN>>>(
        P, v, Ot, S_, S_, S_, C_,
        (size_t)S_ * S_, (size_t)C_ * S_, (size_t)S_ * C_, nullptr, nullptr, 0);
    // 9) out[b][o][s] = Wp @ Ot^T + b_proj[o] + x          M=384 N=4096 K=384
    mma_gemm<4><<<dim3(32, 3, B_), 128, SMEM_DYN>>>(
        wp, Ot, out, C_, C_, C_, S_,
        0, (size_t)S_ * C_, (size_t)C_ * S_, b_proj, x, (size_t)C_ * S_);
}

// round 12
// speedup vs baseline: 1.1400x; 1.1400x over previous
#include <cuda_runtime.h>
#include <cuda_bf16.h>
#include <cstdint>
#include <cstddef>

// Problem constants
#define B_   4
#define C_   384
#define S_   4096

typedef __nv_bfloat16 bf16;

// ---------------------------------------------------------------------------
// Scratch (device globals; no allocation allowed in kernel_launch)
// ---------------------------------------------------------------------------
__device__ float g_scl[B_ * S_];                          // per-pixel rms scale
__device__ bf16  g_wg [3 * C_ * C_];                      // bf16(w_qkv * gamma)
__device__ bf16  g_wp [C_ * C_];                          // bf16(w_proj)
__device__ bf16  g_xnt[(size_t)B_ * S_ * C_];             // [b][s][c] normed x
__device__ bf16  g_qkt[(size_t)B_ * S_ * 2 * C_];         // [b][s][q|k]
__device__ bf16  g_v  [(size_t)B_ * C_ * S_];             // [b][c][s]
__device__ bf16  g_P  [(size_t)B_ * S_ * S_];             // [b][i][j]
__device__ bf16  g_Ot [(size_t)B_ * S_ * C_];             // [b][s][c]

// ---------------------------------------------------------------------------
// PTX helpers (baseline ISA only)
// ---------------------------------------------------------------------------
#define CP_ASYNC16(dst, src) \
    asm volatile("cp.async.cg.shared.global [%0], [%1], 16;" :: "r"(dst), "l"(src))
#define CP_COMMIT() asm volatile("cp.async.commit_group;" ::: "memory")
#define CP_WAIT(n)  asm volatile("cp.async.wait_group %0;" :: "n"(n) : "memory")

__device__ __forceinline__ void ldsm4(uint32_t& r0, uint32_t& r1, uint32_t& r2,
                                      uint32_t& r3, uint32_t addr) {
    asm volatile("ldmatrix.sync.aligned.m8n8.x4.shared.b16 {%0,%1,%2,%3}, [%4];"
                 : "=r"(r0), "=r"(r1), "=r"(r2), "=r"(r3) : "r"(addr));
}

__device__ __forceinline__ void mma16(float* c, const uint32_t* a, const uint32_t* b) {
    asm volatile(
        "mma.sync.aligned.m16n8k16.row.col.f32.bf16.bf16.f32 "
        "{%0,%1,%2,%3}, {%4,%5,%6,%7}, {%8,%9}, {%0,%1,%2,%3};"
        : "+f"(c[0]), "+f"(c[1]), "+f"(c[2]), "+f"(c[3])
        : "r"(a[0]), "r"(a[1]), "r"(a[2]), "r"(a[3]), "r"(b[0]), "r"(b[1]));
}

// ---------------------------------------------------------------------------
// Prep kernels
// ---------------------------------------------------------------------------
__global__ void wg_kernel(bf16* __restrict__ wg, const float* __restrict__ w,
                          const float* __restrict__ g) {
    int i = blockIdx.x * 256 + threadIdx.x;
    if (i < 3 * C_ * C_) wg[i] = __float2bfloat16_rn(w[i] * g[i % C_]);
}

__global__ void wp_kernel(bf16* __restrict__ wp, const float* __restrict__ w) {
    int i = blockIdx.x * 256 + threadIdx.x;
    if (i < C_ * C_) wp[i] = __float2bfloat16_rn(w[i]);
}

__global__ void scale_kernel(float* __restrict__ scl, const float* __restrict__ x) {
    int s = blockIdx.x * 256 + threadIdx.x;
    int b = blockIdx.y;
    const float* xb = x + (size_t)b * C_ * S_ + s;
    float acc = 0.f;
#pragma unroll 8
    for (int c = 0; c < C_; ++c) {
        float v = xb[(size_t)c * S_];
        acc += v * v;
    }
    float l2 = sqrtf(acc);
    scl[b * S_ + s] = 19.595917942265423f / fmaxf(l2, 1e-12f);  // sqrt(384)/max(l2,eps)
}

// transpose + scale: xnt[b][s][c] = bf16(x[b][c][s] * scl[b][s])
__global__ void xnt_kernel(bf16* __restrict__ xnt, const float* __restrict__ x,
                           const float* __restrict__ scl) {
    __shared__ float t[32][33];
    int b = blockIdx.z;
    int s0 = blockIdx.x * 32, c0 = blockIdx.y * 32;
    int tx = threadIdx.x, ty = threadIdx.y;   // 32 x 8
    const float* xb = x + (size_t)b * C_ * S_;
#pragma unroll
    for (int i = 0; i < 4; ++i)
        t[ty + i * 8][tx] = xb[(size_t)(c0 + ty + i * 8) * S_ + s0 + tx];
    __syncthreads();
    bf16* o = xnt + (size_t)b * S_ * C_;
#pragma unroll
    for (int i = 0; i < 4; ++i) {
        int s = s0 + ty + i * 8;
        o[(size_t)s * C_ + c0 + tx] =
            __float2bfloat16_rn(t[tx][ty + i * 8] * scl[b * S_ + s]);
    }
}

// ---------------------------------------------------------------------------
// Warp-MMA bf16 GEMM: D[m][n] = sum_k A[m][k]*B[n][k]
// 128x128 block tile, 8 warps (4M x 2N, warp tile 32x64) — R8-proven layout.
// Kc=64 per stage (4 k16 steps), 3-stage cp.async pipeline (108KB smem,
// 2 CTA/SM), wait(1): halves barrier count vs Kc=32/NSTG=4 at equal regs.
//   EPI 0: +e2[n]  -> bf16   (qk bias)
//   EPI 1: +e2[m]  -> bf16   (v bias)
//   EPI 2: *1/sqrt(C) -> bf16 (scores)
//   EPI 3: plain   -> bf16   (AV -> Ot)
//   EPI 4: +e2[m] + e3[m*ldc+n] -> fp32 (proj bias + residual)
// All M,N multiples of 128; K multiple of 64.
// ---------------------------------------------------------------------------
#define SRB    144                   // bytes per smem row (128 data + 16 pad)
#define ATILEB (128 * SRB)           // 18432 B per operand tile
#define STGB   (2 * ATILEB)          // 36864 B per stage
#define NSTG   3

template <int EPI>
__global__ __launch_bounds__(256)
void mma_gemm(const bf16* __restrict__ Ag, const bf16* __restrict__ Bg,
              void* __restrict__ Cgv, int K, int lda, int ldb, int ldc,
              size_t sA, size_t sB, size_t sC,
              const float* __restrict__ e2, const float* __restrict__ e3,
              size_t e3s)
{
    extern __shared__ __align__(16) char smem[];   // NSTG * STGB bytes

    const int tid  = threadIdx.x;
    const int lane = tid & 31, wid = tid >> 5;
    const int warpM = wid & 3, warpN = wid >> 2;
    const int bz = blockIdx.z;
    const int m0 = blockIdx.y * 128, n0 = blockIdx.x * 128;

    const bf16* A  = Ag + (size_t)bz * sA + (size_t)m0 * lda;
    const bf16* Bp = Bg + (size_t)bz * sB + (size_t)n0 * ldb;
    const uint32_t smB = (uint32_t)__cvta_generic_to_shared(smem);

    // global->smem loader: thread covers rows lr+{0,32,64,96}, one 16B chunk
    // at byte column (tid&7)*16 of the 128B-wide k-slab.
    const int lr = tid >> 3;                         // 0..31
    const int lq = (tid & 7) * 8;                    // halfs
    const uint32_t lqB = (uint32_t)(tid & 7) * 16;   // bytes

    // ldmatrix per-thread source offsets (bytes within a stage)
    const int g = lane >> 3, r = lane & 7;
    const uint32_t aOff = (uint32_t)((warpM * 32 + (g & 1) * 8 + r) * SRB + (g >> 1) * 16);
    const uint32_t bOff = (uint32_t)(ATILEB + (warpN * 64 + (g & 1) * 8 + r) * SRB + (g >> 1) * 16);

    float acc[2][8][4];
#pragma unroll
    for (int mf = 0; mf < 2; ++mf)
#pragma unroll
        for (int nf = 0; nf < 8; ++nf)
#pragma unroll
            for (int i = 0; i < 4; ++i) acc[mf][nf][i] = 0.f;

    const int nK = K >> 6;   // Kc = 64

    auto LOAD = [&](int s, int p) {
        const bf16* As = A  + (size_t)lr * lda + s * 64 + lq;
        const bf16* Bs = Bp + (size_t)lr * ldb + s * 64 + lq;
        uint32_t dA = smB + (uint32_t)(p * STGB + lr * SRB) + lqB;
        uint32_t dB = dA + (uint32_t)ATILEB;
#pragma unroll
        for (int rr = 0; rr < 4; ++rr) {
            CP_ASYNC16(dA + rr * 32 * SRB, As + (size_t)(rr * 32) * lda);
            CP_ASYNC16(dB + rr * 32 * SRB, Bs + (size_t)(rr * 32) * ldb);
        }
    };

    LOAD(0, 0); CP_COMMIT();
    LOAD(1, 1); CP_COMMIT();

    int pc = 0;                       // buffer of stage s
    int pn = 2;                       // buffer for stage s+2
    for (int s = 0; s < nK; ++s) {
        CP_WAIT(1);              // stage s landed (s+1 may be in flight)
        __syncthreads();         // visibility + buffer-reuse fence
        if (s + 2 < nK) LOAD(s + 2, pn);
        CP_COMMIT();             // empty group at tail keeps counts uniform

        const uint32_t pb = smB + (uint32_t)(pc * STGB);
#pragma unroll
        for (int kk = 0; kk < 4; ++kk) {      // four k16 steps per stage
            uint32_t afr[2][4], bfr[8][2];
#pragma unroll
            for (int mf = 0; mf < 2; ++mf)
                ldsm4(afr[mf][0], afr[mf][1], afr[mf][2], afr[mf][3],
                      pb + aOff + (uint32_t)(mf * 16 * SRB + kk * 32));
#pragma unroll
            for (int pr = 0; pr < 4; ++pr)
                ldsm4(bfr[2 * pr][0], bfr[2 * pr + 1][0],
                      bfr[2 * pr][1], bfr[2 * pr + 1][1],
                      pb + bOff + (uint32_t)(pr * 16 * SRB + kk * 32));
#pragma unroll
            for (int mf = 0; mf < 2; ++mf)
#pragma unroll
                for (int nf = 0; nf < 8; ++nf)
                    mma16(acc[mf][nf], afr[mf], bfr[nf]);
        }
        pc = (pc == 2) ? 0 : pc + 1;
        pn = (pn == 2) ? 0 : pn + 1;
    }

    // ---- epilogue ----
    const int rBase = m0 + warpM * 32 + (lane >> 2);
    const int cBase = n0 + warpN * 64 + (lane & 3) * 2;
#pragma unroll
    for (int mf = 0; mf < 2; ++mf) {
#pragma unroll
        for (int h = 0; h < 2; ++h) {
            const int row = rBase + mf * 16 + h * 8;
            float bm = 0.f;
            if (EPI == 1 || EPI == 4) bm = e2[row];
#pragma unroll
            for (int nf = 0; nf < 8; ++nf) {
                const int col = cBase + nf * 8;
                float u0 = acc[mf][nf][2 * h];
                float u1 = acc[mf][nf][2 * h + 1];
                float2 o;
                if (EPI == 0) {
                    float2 bn = *(const float2*)(e2 + col);
                    o.x = u0 + bn.x; o.y = u1 + bn.y;
                } else if (EPI == 1) {
                    o.x = u0 + bm; o.y = u1 + bm;
                } else if (EPI == 2) {
                    const float sc = 0.05103103630798288f;   // 1/sqrt(384)
                    o.x = u0 * sc; o.y = u1 * sc;
                } else if (EPI == 3) {
                    o.x = u0; o.y = u1;
                } else {
                    const float* e3row = e3 + (size_t)bz * e3s + (size_t)row * ldc;
                    float2 rx = *(const float2*)(e3row + col);
                    o.x = u0 + bm + rx.x; o.y = u1 + bm + rx.y;
                }
                if (EPI == 4) {
                    float* Crow = (float*)Cgv + (size_t)bz * sC + (size_t)row * ldc;
                    *(float2*)(Crow + col) = o;
                } else {
                    bf16* Crow = (bf16*)Cgv + (size_t)bz * sC + (size_t)row * ldc;
                    __nv_bfloat162 hv = __floats2bfloat162_rn(o.x, o.y);
                    *(__nv_bfloat162*)(Crow + col) = hv;
                }
            }
        }
    }
}

// ---------------------------------------------------------------------------
// Row softmax over 4096 bf16 columns, one block (256 thr) per row.
// ---------------------------------------------------------------------------
__global__ void softmax_kernel(bf16* __restrict__ P) {
    uint4* p = reinterpret_cast<uint4*>(P + (size_t)blockIdx.x * S_);
    const int t = threadIdx.x;

    uint4 u[2] = { p[t], p[t + 256] };
    float f[16];
#pragma unroll
    for (int i = 0; i < 2; ++i) {
        const uint32_t* w = (const uint32_t*)&u[i];
#pragma unroll
        for (int j = 0; j < 4; ++j) {
            float2 d = __bfloat1622float2(*(const __nv_bfloat162*)&w[j]);
            f[i * 8 + 2 * j] = d.x;
            f[i * 8 + 2 * j + 1] = d.y;
        }
    }

    float mx = -3.4e38f;
#pragma unroll
    for (int i = 0; i < 16; ++i) mx = fmaxf(mx, f[i]);

    __shared__ float redMax[8];
    __shared__ float redSum[8];
#pragma unroll
    for (int o = 16; o > 0; o >>= 1)
        mx = fmaxf(mx, __shfl_xor_sync(0xffffffffu, mx, o));
    if ((t & 31) == 0) redMax[t >> 5] = mx;
    __syncthreads();
    mx = redMax[0];
#pragma unroll
    for (int w = 1; w < 8; ++w) mx = fmaxf(mx, redMax[w]);

    float sum = 0.f;
#pragma unroll
    for (int i = 0; i < 16; ++i) {
        f[i] = __expf(f[i] - mx);
        sum += f[i];
    }
#pragma unroll
    for (int o = 16; o > 0; o >>= 1)
        sum += __shfl_xor_sync(0xffffffffu, sum, o);
    if ((t & 31) == 0) redSum[t >> 5] = sum;
    __syncthreads();
    sum = (redSum[0] + redSum[1]) + (redSum[2] + redSum[3]) +
          (redSum[4] + redSum[5]) + (redSum[6] + redSum[7]);
    float inv = 1.f / sum;

#pragma unroll
    for (int i = 0; i < 2; ++i) {
        uint32_t* w = (uint32_t*)&u[i];
#pragma unroll
        for (int j = 0; j < 4; ++j) {
            __nv_bfloat162 hv = __floats2bfloat162_rn(f[i * 8 + 2 * j] * inv,
                                                      f[i * 8 + 2 * j + 1] * inv);
            w[j] = *(const uint32_t*)&hv;
        }
    }
    p[t] = u[0];
    p[t + 256] = u[1];
}

// ---------------------------------------------------------------------------
// Launch
// ---------------------------------------------------------------------------
extern "C" void kernel_launch(void* const* d_in, const int* in_sizes, int n_in,
                              void* d_out, int out_size) {
    const float* x      = (const float*)d_in[0];   // [4,384,64,64]
    const float* gamma  = (const float*)d_in[1];   // [384]
    const float* w_qkv  = (const float*)d_in[2];   // [1152,384]
    const float* b_qkv  = (const float*)d_in[3];   // [1152]
    const float* w_proj = (const float*)d_in[4];   // [384,384]
    const float* b_proj = (const float*)d_in[5];   // [384]
    float* out = (float*)d_out;                    // [4,384,64,64]

    float *scl;
    bf16 *wg, *wp, *xnt, *qkt, *v, *P, *Ot;
    cudaGetSymbolAddress((void**)&scl, g_scl);
    cudaGetSymbolAddress((void**)&wg,  g_wg);
    cudaGetSymbolAddress((void**)&wp,  g_wp);
    cudaGetSymbolAddress((void**)&xnt, g_xnt);
    cudaGetSymbolAddress((void**)&qkt, g_qkt);
    cudaGetSymbolAddress((void**)&v,   g_v);
    cudaGetSymbolAddress((void**)&P,   g_P);
    cudaGetSymbolAddress((void**)&Ot,  g_Ot);

    const int SMEM_DYN = NSTG * STGB;   // 110592 bytes
    cudaFuncSetAttribute((const void*)mma_gemm<0>, cudaFuncAttributeMaxDynamicSharedMemorySize, SMEM_DYN);
    cudaFuncSetAttribute((const void*)mma_gemm<1>, cudaFuncAttributeMaxDynamicSharedMemorySize, SMEM_DYN);
    cudaFuncSetAttribute((const void*)mma_gemm<2>, cudaFuncAttributeMaxDynamicSharedMemorySize, SMEM_DYN);
    cudaFuncSetAttribute((const void*)mma_gemm<3>, cudaFuncAttributeMaxDynamicSharedMemorySize, SMEM_DYN);
    cudaFuncSetAttribute((const void*)mma_gemm<4>, cudaFuncAttributeMaxDynamicSharedMemorySize, SMEM_DYN);

    // 1) fold gamma into w_qkv (bf16); convert w_proj (bf16)
    wg_kernel<<<(3 * C_ * C_ + 255) / 256, 256>>>(wg, w_qkv, gamma);
    wp_kernel<<<(C_ * C_ + 255) / 256, 256>>>(wp, w_proj);
    // 2) per-pixel rms scale
    scale_kernel<<<dim3(S_ / 256, B_), 256>>>(scl, x);
    // 3) xnt[b][s][c] = bf16(x[b][c][s] * scl)
    xnt_kernel<<<dim3(S_ / 32, C_ / 32, B_), dim3(32, 8)>>>(xnt, x, scl);
    // 4) qk_t[b][s][o] = xnt @ wg[0:768]^T + b_qkv[o]      M=4096 N=768 K=384
    mma_gemm<0><<<dim3(6, 32, B_), 256, SMEM_DYN>>>(
        xnt, wg, qkt, C_, C_, C_, 2 * C_,
        (size_t)S_ * C_, 0, (size_t)S_ * 2 * C_, b_qkv, nullptr, 0);
    // 5) v[b][c][s] = wg[768:] @ xnt^T + b_qkv[768+c]      M=384 N=4096 K=384
    mma_gemm<1><<<dim3(32, 3, B_), 256, SMEM_DYN>>>(
        wg + (size_t)2 * C_ * C_, xnt, v, C_, C_, C_, S_,
        0, (size_t)S_ * C_, (size_t)C_ * S_, b_qkv + 2 * C_, nullptr, 0);
    // 6) P[b][i][j] = q_i . k_j / sqrt(C)                  M=N=4096 K=384
    mma_gemm<2><<<dim3(32, 32, B_), 256, SMEM_DYN>>>(
        qkt, qkt + C_, P, C_, 2 * C_, 2 * C_, S_,
        (size_t)S_ * 2 * C_, (size_t)S_ * 2 * C_, (size_t)S_ * S_, nullptr, nullptr, 0);
    // 7) softmax rows
    softmax_kernel<<<B_ * S_, 256>>>(P);
    // 8) Ot[b][i][c] = P @ v^T                             M=4096 N=384 K=4096
    mma_gemm<3><<<dim3(3, 32, B_), 256, SMEM_DYN>>>(
        P, v, Ot, S_, S_, S_, C_,
        (size_t)S_ * S_, (size_t)C_ * S_, (size_t)S_ * C_, nullptr, nullptr, 0);
    // 9) out[b][o][s] = Wp @ Ot^T + b_proj[o] + x          M=384 N=4096 K=384
    mma_gemm<4><<<dim3(32, 3, B_), 256, SMEM_DYN>>>(
        wp, Ot, out, C_, C_, C_, S_,
        0, (size_t)S_ * C_, (size_t)C_ * S_, b_proj, x, (size_t)C_ * S_);
}

// round 13
// speedup vs baseline: 1.2126x; 1.0637x over previous
#include <cuda_runtime.h>
#include <cuda_bf16.h>
#include <cstdint>
#include <cstddef>

// Problem constants
#define B_   4
#define C_   384
#define S_   4096

typedef __nv_bfloat16 bf16;

// ---------------------------------------------------------------------------
// Scratch (device globals; no allocation allowed in kernel_launch)
// ---------------------------------------------------------------------------
__device__ float g_scl[B_ * S_];                          // per-pixel rms scale
__device__ float g_rs [B_ * S_];                          // softmax row sums
__device__ bf16  g_wg [3 * C_ * C_];                      // bf16(w_qkv * gamma)
__device__ bf16  g_wp [C_ * C_];                          // bf16(w_proj)
__device__ bf16  g_xnt[(size_t)B_ * S_ * C_];             // [b][s][c] normed x
__device__ bf16  g_qkt[(size_t)B_ * S_ * 2 * C_];         // [b][s][q|k]
__device__ bf16  g_v  [(size_t)B_ * C_ * S_];             // [b][c][s]
__device__ bf16  g_P  [(size_t)B_ * S_ * S_];             // [b][i][j] exp-scores
__device__ bf16  g_Ot [(size_t)B_ * S_ * C_];             // [b][s][c]

// ---------------------------------------------------------------------------
// PTX helpers (baseline ISA only)
// ---------------------------------------------------------------------------
#define CP_ASYNC16(dst, src) \
    asm volatile("cp.async.cg.shared.global [%0], [%1], 16;" :: "r"(dst), "l"(src))
#define CP_COMMIT() asm volatile("cp.async.commit_group;" ::: "memory")
#define CP_WAIT(n)  asm volatile("cp.async.wait_group %0;" :: "n"(n) : "memory")

__device__ __forceinline__ void ldsm4(uint32_t& r0, uint32_t& r1, uint32_t& r2,
                                      uint32_t& r3, uint32_t addr) {
    asm volatile("ldmatrix.sync.aligned.m8n8.x4.shared.b16 {%0,%1,%2,%3}, [%4];"
                 : "=r"(r0), "=r"(r1), "=r"(r2), "=r"(r3) : "r"(addr));
}

__device__ __forceinline__ void mma16(float* c, const uint32_t* a, const uint32_t* b) {
    asm volatile(
        "mma.sync.aligned.m16n8k16.row.col.f32.bf16.bf16.f32 "
        "{%0,%1,%2,%3}, {%4,%5,%6,%7}, {%8,%9}, {%0,%1,%2,%3};"
        : "+f"(c[0]), "+f"(c[1]), "+f"(c[2]), "+f"(c[3])
        : "r"(a[0]), "r"(a[1]), "r"(a[2]), "r"(a[3]), "r"(b[0]), "r"(b[1]));
}

// ---------------------------------------------------------------------------
// Prep kernels
// ---------------------------------------------------------------------------
__global__ void wg_kernel(bf16* __restrict__ wg, const float* __restrict__ w,
                          const float* __restrict__ g) {
    int i = blockIdx.x * 256 + threadIdx.x;
    if (i < 3 * C_ * C_) wg[i] = __float2bfloat16_rn(w[i] * g[i % C_]);
}

__global__ void wp_kernel(bf16* __restrict__ wp, const float* __restrict__ w) {
    int i = blockIdx.x * 256 + threadIdx.x;
    if (i < C_ * C_) wp[i] = __float2bfloat16_rn(w[i]);
}

__global__ void zero_rs(float* __restrict__ rs) {
    rs[blockIdx.x * 256 + threadIdx.x] = 0.f;
}

__global__ void scale_kernel(float* __restrict__ scl, const float* __restrict__ x) {
    int s = blockIdx.x * 256 + threadIdx.x;
    int b = blockIdx.y;
    const float* xb = x + (size_t)b * C_ * S_ + s;
    float acc = 0.f;
#pragma unroll 8
    for (int c = 0; c < C_; ++c) {
        float v = xb[(size_t)c * S_];
        acc += v * v;
    }
    float l2 = sqrtf(acc);
    scl[b * S_ + s] = 19.595917942265423f / fmaxf(l2, 1e-12f);  // sqrt(384)/max(l2,eps)
}

// transpose + scale: xnt[b][s][c] = bf16(x[b][c][s] * scl[b][s])
__global__ void xnt_kernel(bf16* __restrict__ xnt, const float* __restrict__ x,
                           const float* __restrict__ scl) {
    __shared__ float t[32][33];
    int b = blockIdx.z;
    int s0 = blockIdx.x * 32, c0 = blockIdx.y * 32;
    int tx = threadIdx.x, ty = threadIdx.y;   // 32 x 8
    const float* xb = x + (size_t)b * C_ * S_;
#pragma unroll
    for (int i = 0; i < 4; ++i)
        t[ty + i * 8][tx] = xb[(size_t)(c0 + ty + i * 8) * S_ + s0 + tx];
    __syncthreads();
    bf16* o = xnt + (size_t)b * S_ * C_;
#pragma unroll
    for (int i = 0; i < 4; ++i) {
        int s = s0 + ty + i * 8;
        o[(size_t)s * C_ + c0 + tx] =
            __float2bfloat16_rn(t[tx][ty + i * 8] * scl[b * S_ + s]);
    }
}

// ---------------------------------------------------------------------------
// Warp-MMA bf16 GEMM: D[m][n] = sum_k A[m][k]*B[n][k]
// 128x128 block tile, 8 warps (4M x 2N, warp tile 32x64), Kc=32 (2 k16 steps),
// 4-stage cp.async pipeline, ldmatrix operand fetch, fp32 accumulate.
// (R8-proven mainloop — unchanged.)
//   EPI 0: +e2[n]  -> bf16   (qk bias)
//   EPI 1: +e2[m]  -> bf16   (v bias)
//   EPI 2: exp(acc/sqrt(C)) -> bf16, atomicAdd row sums into e3 (scores)
//   EPI 3: * 1/e3[row] -> bf16  (AV normalize by softmax row sum)
//   EPI 4: +e2[m] + e3[m*ldc+n] -> fp32 (proj bias + residual)
// All M,N multiples of 128; K multiple of 32.
// ---------------------------------------------------------------------------
#define SRB    80                    // bytes per smem row (64 data + 16 pad)
#define ATILEB (128 * SRB)           // 10240 B per operand tile
#define STGB   (2 * ATILEB)          // 20480 B per stage
#define NSTG   4

template <int EPI>
__global__ __launch_bounds__(256)
void mma_gemm(const bf16* __restrict__ Ag, const bf16* __restrict__ Bg,
              void* __restrict__ Cgv, int K, int lda, int ldb, int ldc,
              size_t sA, size_t sB, size_t sC,
              const float* __restrict__ e2, const float* __restrict__ e3,
              size_t e3s)
{
    extern __shared__ __align__(16) char smem[];   // NSTG * STGB bytes

    const int tid  = threadIdx.x;
    const int lane = tid & 31, wid = tid >> 5;
    const int warpM = wid & 3, warpN = wid >> 2;
    const int bz = blockIdx.z;
    const int m0 = blockIdx.y * 128, n0 = blockIdx.x * 128;

    const bf16* A  = Ag + (size_t)bz * sA + (size_t)m0 * lda;
    const bf16* Bp = Bg + (size_t)bz * sB + (size_t)n0 * ldb;
    const uint32_t smB = (uint32_t)__cvta_generic_to_shared(smem);

    // global->smem loader: thread covers rows lr and lr+64, 16B at k-halfs lq
    const int lr = tid >> 2;
    const int lq = (tid & 3) * 8;                    // halfs
    const uint32_t lqB = (uint32_t)(tid & 3) * 16;   // bytes

    // ldmatrix per-thread source offsets (bytes within a stage)
    const int g = lane >> 3, r = lane & 7;
    const uint32_t aOff = (uint32_t)((warpM * 32 + (g & 1) * 8 + r) * SRB + (g >> 1) * 16);
    const uint32_t bOff = (uint32_t)(ATILEB + (warpN * 64 + (g & 1) * 8 + r) * SRB + (g >> 1) * 16);

    float acc[2][8][4];
#pragma unroll
    for (int mf = 0; mf < 2; ++mf)
#pragma unroll
        for (int nf = 0; nf < 8; ++nf)
#pragma unroll
            for (int i = 0; i < 4; ++i) acc[mf][nf][i] = 0.f;

    const int nK = K >> 5;   // Kc = 32

    auto LOAD = [&](int s) {
        const int p = s & (NSTG - 1);
        const bf16* As = A  + (size_t)lr * lda + s * 32 + lq;
        const bf16* Bs = Bp + (size_t)lr * ldb + s * 32 + lq;
        uint32_t dA = smB + (uint32_t)(p * STGB + lr * SRB) + lqB;
        uint32_t dB = dA + (uint32_t)ATILEB;
        CP_ASYNC16(dA,                As);
        CP_ASYNC16(dA + 64 * SRB,     As + (size_t)64 * lda);
        CP_ASYNC16(dB,                Bs);
        CP_ASYNC16(dB + 64 * SRB,     Bs + (size_t)64 * ldb);
    };

    LOAD(0); CP_COMMIT();
    LOAD(1); CP_COMMIT();
    LOAD(2); CP_COMMIT();

    for (int s = 0; s < nK; ++s) {
        CP_WAIT(2);              // stage s landed
        __syncthreads();         // visibility + buffer-reuse fence
        if (s + 3 < nK) LOAD(s + 3);
        CP_COMMIT();             // empty group at tail keeps counts uniform

        const uint32_t pb = smB + (uint32_t)((s & (NSTG - 1)) * STGB);
#pragma unroll
        for (int kk = 0; kk < 2; ++kk) {      // two k16 steps per stage
            uint32_t afr[2][4], bfr[8][2];
#pragma unroll
            for (int mf = 0; mf < 2; ++mf)
                ldsm4(afr[mf][0], afr[mf][1], afr[mf][2], afr[mf][3],
                      pb + aOff + (uint32_t)(mf * 16 * SRB + kk * 32));
#pragma unroll
            for (int pr = 0; pr < 4; ++pr)
                ldsm4(bfr[2 * pr][0], bfr[2 * pr + 1][0],
                      bfr[2 * pr][1], bfr[2 * pr + 1][1],
                      pb + bOff + (uint32_t)(pr * 16 * SRB + kk * 32));
#pragma unroll
            for (int mf = 0; mf < 2; ++mf)
#pragma unroll
                for (int nf = 0; nf < 8; ++nf)
                    mma16(acc[mf][nf], afr[mf], bfr[nf]);
        }
    }

    // ---- epilogue ----
    const int rBase = m0 + warpM * 32 + (lane >> 2);
    const int cBase = n0 + warpN * 64 + (lane & 3) * 2;
#pragma unroll
    for (int mf = 0; mf < 2; ++mf) {
#pragma unroll
        for (int h = 0; h < 2; ++h) {
            const int row = rBase + mf * 16 + h * 8;
            float bm = 0.f;
            if (EPI == 1 || EPI == 4) bm = e2[row];
            float inv = 1.f;
            if (EPI == 3) inv = 1.f / e3[(size_t)bz * e3s + row];
            float rsum = 0.f;
#pragma unroll
            for (int nf = 0; nf < 8; ++nf) {
                const int col = cBase + nf * 8;
                float u0 = acc[mf][nf][2 * h];
                float u1 = acc[mf][nf][2 * h + 1];
                float2 o;
                if (EPI == 0) {
                    float2 bn = *(const float2*)(e2 + col);
                    o.x = u0 + bn.x; o.y = u1 + bn.y;
                } else if (EPI == 1) {
                    o.x = u0 + bm; o.y = u1 + bm;
                } else if (EPI == 2) {
                    const float sc = 0.05103103630798288f;   // 1/sqrt(384)
                    o.x = __expf(u0 * sc); o.y = __expf(u1 * sc);
                    rsum += o.x + o.y;
                } else if (EPI == 3) {
                    o.x = u0 * inv; o.y = u1 * inv;
                } else {
                    const float* e3row = e3 + (size_t)bz * e3s + (size_t)row * ldc;
                    float2 rx = *(const float2*)(e3row + col);
                    o.x = u0 + bm + rx.x; o.y = u1 + bm + rx.y;
                }
                if (EPI == 4) {
                    float* Crow = (float*)Cgv + (size_t)bz * sC + (size_t)row * ldc;
                    *(float2*)(Crow + col) = o;
                } else {
                    bf16* Crow = (bf16*)Cgv + (size_t)bz * sC + (size_t)row * ldc;
                    __nv_bfloat162 hv = __floats2bfloat162_rn(o.x, o.y);
                    *(__nv_bfloat162*)(Crow + col) = hv;
                }
            }
            if (EPI == 2) {
                // reduce the 4 lanes sharing this row (lane^1, lane^2 keep lane>>2)
                rsum += __shfl_xor_sync(0xffffffffu, rsum, 1);
                rsum += __shfl_xor_sync(0xffffffffu, rsum, 2);
                if ((lane & 3) == 0)
                    atomicAdd((float*)(e3 + (size_t)bz * e3s + row), rsum);
            }
        }
    }
}

// ---------------------------------------------------------------------------
// Launch
// ---------------------------------------------------------------------------
extern "C" void kernel_launch(void* const* d_in, const int* in_sizes, int n_in,
                              void* d_out, int out_size) {
    const float* x      = (const float*)d_in[0];   // [4,384,64,64]
    const float* gamma  = (const float*)d_in[1];   // [384]
    const float* w_qkv  = (const float*)d_in[2];   // [1152,384]
    const float* b_qkv  = (const float*)d_in[3];   // [1152]
    const float* w_proj = (const float*)d_in[4];   // [384,384]
    const float* b_proj = (const float*)d_in[5];   // [384]
    float* out = (float*)d_out;                    // [4,384,64,64]

    float *scl, *rs;
    bf16 *wg, *wp, *xnt, *qkt, *v, *P, *Ot;
    cudaGetSymbolAddress((void**)&scl, g_scl);
    cudaGetSymbolAddress((void**)&rs,  g_rs);
    cudaGetSymbolAddress((void**)&wg,  g_wg);
    cudaGetSymbolAddress((void**)&wp,  g_wp);
    cudaGetSymbolAddress((void**)&xnt, g_xnt);
    cudaGetSymbolAddress((void**)&qkt, g_qkt);
    cudaGetSymbolAddress((void**)&v,   g_v);
    cudaGetSymbolAddress((void**)&P,   g_P);
    cudaGetSymbolAddress((void**)&Ot,  g_Ot);

    const int SMEM_DYN = NSTG * STGB;   // 81920 bytes
    cudaFuncSetAttribute((const void*)mma_gemm<0>, cudaFuncAttributeMaxDynamicSharedMemorySize, SMEM_DYN);
    cudaFuncSetAttribute((const void*)mma_gemm<1>, cudaFuncAttributeMaxDynamicSharedMemorySize, SMEM_DYN);
    cudaFuncSetAttribute((const void*)mma_gemm<2>, cudaFuncAttributeMaxDynamicSharedMemorySize, SMEM_DYN);
    cudaFuncSetAttribute((const void*)mma_gemm<3>, cudaFuncAttributeMaxDynamicSharedMemorySize, SMEM_DYN);
    cudaFuncSetAttribute((const void*)mma_gemm<4>, cudaFuncAttributeMaxDynamicSharedMemorySize, SMEM_DYN);

    // 1) fold gamma into w_qkv (bf16); convert w_proj (bf16); zero row sums
    wg_kernel<<<(3 * C_ * C_ + 255) / 256, 256>>>(wg, w_qkv, gamma);
    wp_kernel<<<(C_ * C_ + 255) / 256, 256>>>(wp, w_proj);
    zero_rs<<<B_ * S_ / 256, 256>>>(rs);
    // 2) per-pixel rms scale
    scale_kernel<<<dim3(S_ / 256, B_), 256>>>(scl, x);
    // 3) xnt[b][s][c] = bf16(x[b][c][s] * scl)
    xnt_kernel<<<dim3(S_ / 32, C_ / 32, B_), dim3(32, 8)>>>(xnt, x, scl);
    // 4) qk_t[b][s][o] = xnt @ wg[0:768]^T + b_qkv[o]      M=4096 N=768 K=384
    mma_gemm<0><<<dim3(6, 32, B_), 256, SMEM_DYN>>>(
        xnt, wg, qkt, C_, C_, C_, 2 * C_,
        (size_t)S_ * C_, 0, (size_t)S_ * 2 * C_, b_qkv, nullptr, 0);
    // 5) v[b][c][s] = wg[768:] @ xnt^T + b_qkv[768+c]      M=384 N=4096 K=384
    mma_gemm<1><<<dim3(32, 3, B_), 256, SMEM_DYN>>>(
        wg + (size_t)2 * C_ * C_, xnt, v, C_, C_, C_, S_,
        0, (size_t)S_ * C_, (size_t)C_ * S_, b_qkv + 2 * C_, nullptr, 0);
    // 6) P[b][i][j] = exp(q_i . k_j / sqrt(C)); rs[b][i] += row sums
    //    (softmax shift-free: |scores| <= ~20, exp safely in fp32/bf16 range)
    mma_gemm<2><<<dim3(32, 32, B_), 256, SMEM_DYN>>>(
        qkt, qkt + C_, P, C_, 2 * C_, 2 * C_, S_,
        (size_t)S_ * 2 * C_, (size_t)S_ * 2 * C_, (size_t)S_ * S_,
        nullptr, rs, S_);
    // 7) Ot[b][i][c] = (P @ v^T) / rs[b][i]                M=4096 N=384 K=4096
    mma_gemm<3><<<dim3(3, 32, B_), 256, SMEM_DYN>>>(
        P, v, Ot, S_, S_, S_, C_,
        (size_t)S_ * S_, (size_t)C_ * S_, (size_t)S_ * C_,
        nullptr, rs, S_);
    // 8) out[b][o][s] = Wp @ Ot^T + b_proj[o] + x          M=384 N=4096 K=384
    mma_gemm<4><<<dim3(32, 3, B_), 256, SMEM_DYN>>>(
        wp, Ot, out, C_, C_, C_, S_,
        0, (size_t)S_ * C_, (size_t)C_ * S_, b_proj, x, (size_t)C_ * S_);
}

// round 14
// speedup vs baseline: 1.2510x; 1.0316x over previous
#include <cuda_runtime.h>
#include <cuda_bf16.h>
#include <cstdint>
#include <cstddef>

// Problem constants
#define B_   4
#define C_   384
#define S_   4096

typedef __nv_bfloat16 bf16;

// ---------------------------------------------------------------------------
// Scratch (device globals; no allocation allowed in kernel_launch)
// ---------------------------------------------------------------------------
__device__ float g_scl[B_ * S_];                          // per-pixel rms scale
__device__ float g_rs [B_ * S_];                          // softmax row sums
__device__ bf16  g_wg [3 * C_ * C_];                      // bf16(w_qkv * gamma)
__device__ bf16  g_wp [C_ * C_];                          // bf16(w_proj)
__device__ bf16  g_xnt[(size_t)B_ * S_ * C_];             // [b][s][c] normed x
__device__ bf16  g_qkt[(size_t)B_ * S_ * 2 * C_];         // [b][s][q|k]
__device__ bf16  g_v  [(size_t)B_ * C_ * S_];             // [b][c][s]
__device__ bf16  g_P  [(size_t)B_ * S_ * S_];             // [b][i][j] exp-scores
__device__ bf16  g_Ot [(size_t)B_ * S_ * C_];             // [b][s][c]

// ---------------------------------------------------------------------------
// PTX helpers (baseline ISA only)
// ---------------------------------------------------------------------------
#define CP_ASYNC16(dst, src) \
    asm volatile("cp.async.cg.shared.global [%0], [%1], 16;" :: "r"(dst), "l"(src))
#define CP_COMMIT() asm volatile("cp.async.commit_group;" ::: "memory")
#define CP_WAIT(n)  asm volatile("cp.async.wait_group %0;" :: "n"(n) : "memory")

__device__ __forceinline__ void ldsm4(uint32_t& r0, uint32_t& r1, uint32_t& r2,
                                      uint32_t& r3, uint32_t addr) {
    asm volatile("ldmatrix.sync.aligned.m8n8.x4.shared.b16 {%0,%1,%2,%3}, [%4];"
                 : "=r"(r0), "=r"(r1), "=r"(r2), "=r"(r3) : "r"(addr));
}

__device__ __forceinline__ void mma16(float* c, const uint32_t* a, const uint32_t* b) {
    asm volatile(
        "mma.sync.aligned.m16n8k16.row.col.f32.bf16.bf16.f32 "
        "{%0,%1,%2,%3}, {%4,%5,%6,%7}, {%8,%9}, {%0,%1,%2,%3};"
        : "+f"(c[0]), "+f"(c[1]), "+f"(c[2]), "+f"(c[3])
        : "r"(a[0]), "r"(a[1]), "r"(a[2]), "r"(a[3]), "r"(b[0]), "r"(b[1]));
}

// ---------------------------------------------------------------------------
// Prep kernels
// ---------------------------------------------------------------------------
__global__ void wg_kernel(bf16* __restrict__ wg, const float* __restrict__ w,
                          const float* __restrict__ g) {
    int i = blockIdx.x * 256 + threadIdx.x;
    if (i < 3 * C_ * C_) wg[i] = __float2bfloat16_rn(w[i] * g[i % C_]);
}

__global__ void wp_kernel(bf16* __restrict__ wp, const float* __restrict__ w) {
    int i = blockIdx.x * 256 + threadIdx.x;
    if (i < C_ * C_) wp[i] = __float2bfloat16_rn(w[i]);
}

__global__ void zero_rs(float* __restrict__ rs) {
    rs[blockIdx.x * 256 + threadIdx.x] = 0.f;
}

// per-pixel rms scale, parallel over channel slices:
// block = (32 s, 8 c-slices); each thread sums 48 channels (MLP ~8).
__global__ void scale_kernel(float* __restrict__ scl, const float* __restrict__ x) {
    __shared__ float red[8][32];
    const int tx = threadIdx.x, ty = threadIdx.y;
    const int s = blockIdx.x * 32 + tx;
    const int b = blockIdx.y;
    const float* xb = x + (size_t)b * C_ * S_ + s;
    float acc = 0.f;
#pragma unroll
    for (int i = 0; i < 48; ++i) {
        float v = xb[(size_t)(ty + i * 8) * S_];
        acc += v * v;
    }
    red[ty][tx] = acc;
    __syncthreads();
    if (ty == 0) {
        float t = red[0][tx];
#pragma unroll
        for (int j = 1; j < 8; ++j) t += red[j][tx];
        float l2 = sqrtf(t);
        scl[b * S_ + s] = 19.595917942265423f / fmaxf(l2, 1e-12f);  // sqrt(384)/max(l2,eps)
    }
}

// transpose + scale: xnt[b][s][c] = bf16(x[b][c][s] * scl[b][s])
__global__ void xnt_kernel(bf16* __restrict__ xnt, const float* __restrict__ x,
                           const float* __restrict__ scl) {
    __shared__ float t[32][33];
    int b = blockIdx.z;
    int s0 = blockIdx.x * 32, c0 = blockIdx.y * 32;
    int tx = threadIdx.x, ty = threadIdx.y;   // 32 x 8
    const float* xb = x + (size_t)b * C_ * S_;
#pragma unroll
    for (int i = 0; i < 4; ++i)
        t[ty + i * 8][tx] = xb[(size_t)(c0 + ty + i * 8) * S_ + s0 + tx];
    __syncthreads();
    bf16* o = xnt + (size_t)b * S_ * C_;
#pragma unroll
    for (int i = 0; i < 4; ++i) {
        int s = s0 + ty + i * 8;
        o[(size_t)s * C_ + c0 + tx] =
            __float2bfloat16_rn(t[tx][ty + i * 8] * scl[b * S_ + s]);
    }
}

// ---------------------------------------------------------------------------
// Warp-MMA bf16 GEMM: D[m][n] = sum_k A[m][k]*B[n][k]
// 128x128 block tile, 8 warps (4M x 2N, warp tile 32x64), Kc=32 (2 k16 steps),
// 4-stage cp.async pipeline, ldmatrix operand fetch, fp32 accumulate.
//   EPI 0: +e2[n]  -> bf16   (qk bias)
//   EPI 1: +e2[m]  -> bf16   (v bias)
//   EPI 2: exp(acc/sqrt(C)) -> bf16, atomicAdd row sums into e3 (scores)
//   EPI 3: * 1/e3[row] -> bf16  (AV normalize by softmax row sum)
//   EPI 4: +e2[m] + e3[m*ldc+n] -> fp32 (proj bias + residual)
// All M,N multiples of 128; K multiple of 32.
// ---------------------------------------------------------------------------
#define SRB    80                    // bytes per smem row (64 data + 16 pad)
#define ATILEB (128 * SRB)           // 10240 B per operand tile
#define STGB   (2 * ATILEB)          // 20480 B per stage
#define NSTG   4

template <int EPI>
__global__ __launch_bounds__(256)
void mma_gemm(const bf16* __restrict__ Ag, const bf16* __restrict__ Bg,
              void* __restrict__ Cgv, int K, int lda, int ldb, int ldc,
              size_t sA, size_t sB, size_t sC,
              const float* __restrict__ e2, const float* __restrict__ e3,
              size_t e3s)
{
    extern __shared__ __align__(16) char smem[];   // NSTG * STGB bytes

    const int tid  = threadIdx.x;
    const int lane = tid & 31, wid = tid >> 5;
    const int warpM = wid & 3, warpN = wid >> 2;
    const int bz = blockIdx.z;
    const int m0 = blockIdx.y * 128, n0 = blockIdx.x * 128;

    const bf16* A  = Ag + (size_t)bz * sA + (size_t)m0 * lda;
    const bf16* Bp = Bg + (size_t)bz * sB + (size_t)n0 * ldb;
    const uint32_t smB = (uint32_t)__cvta_generic_to_shared(smem);

    // global->smem loader: thread covers rows lr and lr+64, 16B at k-halfs lq
    const int lr = tid >> 2;
    const int lq = (tid & 3) * 8;                    // halfs
    const uint32_t lqB = (uint32_t)(tid & 3) * 16;   // bytes

    // ldmatrix per-thread source offsets (bytes within a stage)
    const int g = lane >> 3, r = lane & 7;
    const uint32_t aOff = (uint32_t)((warpM * 32 + (g & 1) * 8 + r) * SRB + (g >> 1) * 16);
    const uint32_t bOff = (uint32_t)(ATILEB + (warpN * 64 + (g & 1) * 8 + r) * SRB + (g >> 1) * 16);

    float acc[2][8][4];
#pragma unroll
    for (int mf = 0; mf < 2; ++mf)
#pragma unroll
        for (int nf = 0; nf < 8; ++nf)
#pragma unroll
            for (int i = 0; i < 4; ++i) acc[mf][nf][i] = 0.f;

    const int nK = K >> 5;   // Kc = 32

    auto LOAD = [&](int s) {
        const int p = s & (NSTG - 1);
        const bf16* As = A  + (size_t)lr * lda + s * 32 + lq;
        const bf16* Bs = Bp + (size_t)lr * ldb + s * 32 + lq;
        uint32_t dA = smB + (uint32_t)(p * STGB + lr * SRB) + lqB;
        uint32_t dB = dA + (uint32_t)ATILEB;
        CP_ASYNC16(dA,                As);
        CP_ASYNC16(dA + 64 * SRB,     As + (size_t)64 * lda);
        CP_ASYNC16(dB,                Bs);
        CP_ASYNC16(dB + 64 * SRB,     Bs + (size_t)64 * ldb);
    };

    LOAD(0); CP_COMMIT();
    LOAD(1); CP_COMMIT();
    LOAD(2); CP_COMMIT();

    for (int s = 0; s < nK; ++s) {
        CP_WAIT(2);              // stage s landed
        __syncthreads();         // visibility + buffer-reuse fence
        if (s + 3 < nK) LOAD(s + 3);
        CP_COMMIT();             // empty group at tail keeps counts uniform

        const uint32_t pb = smB + (uint32_t)((s & (NSTG - 1)) * STGB);
#pragma unroll
        for (int kk = 0; kk < 2; ++kk) {      // two k16 steps per stage
            uint32_t afr[2][4], bfr[8][2];
#pragma unroll
            for (int mf = 0; mf < 2; ++mf)
                ldsm4(afr[mf][0], afr[mf][1], afr[mf][2], afr[mf][3],
                      pb + aOff + (uint32_t)(mf * 16 * SRB + kk * 32));
#pragma unroll
            for (int pr = 0; pr < 4; ++pr)
                ldsm4(bfr[2 * pr][0], bfr[2 * pr + 1][0],
                      bfr[2 * pr][1], bfr[2 * pr + 1][1],
                      pb + bOff + (uint32_t)(pr * 16 * SRB + kk * 32));
#pragma unroll
            for (int mf = 0; mf < 2; ++mf)
#pragma unroll
                for (int nf = 0; nf < 8; ++nf)
                    mma16(acc[mf][nf], afr[mf], bfr[nf]);
        }
    }

    // ---- epilogue ----
    const int rBase = m0 + warpM * 32 + (lane >> 2);
    const int cBase = n0 + warpN * 64 + (lane & 3) * 2;
#pragma unroll
    for (int mf = 0; mf < 2; ++mf) {
#pragma unroll
        for (int h = 0; h < 2; ++h) {
            const int row = rBase + mf * 16 + h * 8;
            float bm = 0.f;
            if (EPI == 1 || EPI == 4) bm = e2[row];
            float inv = 1.f;
            if (EPI == 3) inv = 1.f / e3[(size_t)bz * e3s + row];
            float rsum = 0.f;
#pragma unroll
            for (int nf = 0; nf < 8; ++nf) {
                const int col = cBase + nf * 8;
                float u0 = acc[mf][nf][2 * h];
                float u1 = acc[mf][nf][2 * h + 1];
                float2 o;
                if (EPI == 0) {
                    float2 bn = *(const float2*)(e2 + col);
                    o.x = u0 + bn.x; o.y = u1 + bn.y;
                } else if (EPI == 1) {
                    o.x = u0 + bm; o.y = u1 + bm;
                } else if (EPI == 2) {
                    const float sc = 0.05103103630798288f;   // 1/sqrt(384)
                    o.x = __expf(u0 * sc); o.y = __expf(u1 * sc);
                    rsum += o.x + o.y;
                } else if (EPI == 3) {
                    o.x = u0 * inv; o.y = u1 * inv;
                } else {
                    const float* e3row = e3 + (size_t)bz * e3s + (size_t)row * ldc;
                    float2 rx = *(const float2*)(e3row + col);
                    o.x = u0 + bm + rx.x; o.y = u1 + bm + rx.y;
                }
                if (EPI == 4) {
                    float* Crow = (float*)Cgv + (size_t)bz * sC + (size_t)row * ldc;
                    *(float2*)(Crow + col) = o;
                } else {
                    bf16* Crow = (bf16*)Cgv + (size_t)bz * sC + (size_t)row * ldc;
                    __nv_bfloat162 hv = __floats2bfloat162_rn(o.x, o.y);
                    *(__nv_bfloat162*)(Crow + col) = hv;
                }
            }
            if (EPI == 2) {
                // reduce the 4 lanes sharing this row (lane^1, lane^2 keep lane>>2)
                rsum += __shfl_xor_sync(0xffffffffu, rsum, 1);
                rsum += __shfl_xor_sync(0xffffffffu, rsum, 2);
                if ((lane & 3) == 0)
                    atomicAdd((float*)(e3 + (size_t)bz * e3s + row), rsum);
            }
        }
    }
}

// ---------------------------------------------------------------------------
// Launch
// ---------------------------------------------------------------------------
extern "C" void kernel_launch(void* const* d_in, const int* in_sizes, int n_in,
                              void* d_out, int out_size) {
    const float* x      = (const float*)d_in[0];   // [4,384,64,64]
    const float* gamma  = (const float*)d_in[1];   // [384]
    const float* w_qkv  = (const float*)d_in[2];   // [1152,384]
    const float* b_qkv  = (const float*)d_in[3];   // [1152]
    const float* w_proj = (const float*)d_in[4];   // [384,384]
    const float* b_proj = (const float*)d_in[5];   // [384]
    float* out = (float*)d_out;                    // [4,384,64,64]

    float *scl, *rs;
    bf16 *wg, *wp, *xnt, *qkt, *v, *P, *Ot;
    cudaGetSymbolAddress((void**)&scl, g_scl);
    cudaGetSymbolAddress((void**)&rs,  g_rs);
    cudaGetSymbolAddress((void**)&wg,  g_wg);
    cudaGetSymbolAddress((void**)&wp,  g_wp);
    cudaGetSymbolAddress((void**)&xnt, g_xnt);
    cudaGetSymbolAddress((void**)&qkt, g_qkt);
    cudaGetSymbolAddress((void**)&v,   g_v);
    cudaGetSymbolAddress((void**)&P,   g_P);
    cudaGetSymbolAddress((void**)&Ot,  g_Ot);

    const int SMEM_DYN = NSTG * STGB;   // 81920 bytes
    cudaFuncSetAttribute((const void*)mma_gemm<0>, cudaFuncAttributeMaxDynamicSharedMemorySize, SMEM_DYN);
    cudaFuncSetAttribute((const void*)mma_gemm<1>, cudaFuncAttributeMaxDynamicSharedMemorySize, SMEM_DYN);
    cudaFuncSetAttribute((const void*)mma_gemm<2>, cudaFuncAttributeMaxDynamicSharedMemorySize, SMEM_DYN);
    cudaFuncSetAttribute((const void*)mma_gemm<3>, cudaFuncAttributeMaxDynamicSharedMemorySize, SMEM_DYN);
    cudaFuncSetAttribute((const void*)mma_gemm<4>, cudaFuncAttributeMaxDynamicSharedMemorySize, SMEM_DYN);

    // 1) fold gamma into w_qkv (bf16); convert w_proj (bf16); zero row sums
    wg_kernel<<<(3 * C_ * C_ + 255) / 256, 256>>>(wg, w_qkv, gamma);
    wp_kernel<<<(C_ * C_ + 255) / 256, 256>>>(wp, w_proj);
    zero_rs<<<B_ * S_ / 256, 256>>>(rs);
    // 2) per-pixel rms scale (512 CTAs, MLP~8 per thread)
    scale_kernel<<<dim3(S_ / 32, B_), dim3(32, 8)>>>(scl, x);
    // 3) xnt[b][s][c] = bf16(x[b][c][s] * scl)
    xnt_kernel<<<dim3(S_ / 32, C_ / 32, B_), dim3(32, 8)>>>(xnt, x, scl);
    // 4) qk_t[b][s][o] = xnt @ wg[0:768]^T + b_qkv[o]      M=4096 N=768 K=384
    mma_gemm<0><<<dim3(6, 32, B_), 256, SMEM_DYN>>>(
        xnt, wg, qkt, C_, C_, C_, 2 * C_,
        (size_t)S_ * C_, 0, (size_t)S_ * 2 * C_, b_qkv, nullptr, 0);
    // 5) v[b][c][s] = wg[768:] @ xnt^T + b_qkv[768+c]      M=384 N=4096 K=384
    mma_gemm<1><<<dim3(32, 3, B_), 256, SMEM_DYN>>>(
        wg + (size_t)2 * C_ * C_, xnt, v, C_, C_, C_, S_,
        0, (size_t)S_ * C_, (size_t)C_ * S_, b_qkv + 2 * C_, nullptr, 0);
    // 6) P[b][i][j] = exp(q_i . k_j / sqrt(C)); rs[b][i] += row sums
    mma_gemm<2><<<dim3(32, 32, B_), 256, SMEM_DYN>>>(
        qkt, qkt + C_, P, C_, 2 * C_, 2 * C_, S_,
        (size_t)S_ * 2 * C_, (size_t)S_ * 2 * C_, (size_t)S_ * S_,
        nullptr, rs, S_);
    // 7) Ot[b][i][c] = (P @ v^T) / rs[b][i]                M=4096 N=384 K=4096
    mma_gemm<3><<<dim3(3, 32, B_), 256, SMEM_DYN>>>(
        P, v, Ot, S_, S_, S_, C_,
        (size_t)S_ * S_, (size_t)C_ * S_, (size_t)S_ * C_,
        nullptr, rs, S_);
    // 8) out[b][o][s] = Wp @ Ot^T + b_proj[o] + x          M=384 N=4096 K=384
    mma_gemm<4><<<dim3(32, 3, B_), 256, SMEM_DYN>>>(
        wp, Ot, out, C_, C_, C_, S_,
        0, (size_t)S_ * C_, (size_t)C_ * S_, b_proj, x, (size_t)C_ * S_);
}

// round 15
// speedup vs baseline: 1.2659x; 1.0119x over previous
#include <cuda_runtime.h>
#include <cuda_bf16.h>
#include <cstdint>
#include <cstddef>

// Problem constants
#define B_   4
#define C_   384
#define S_   4096

typedef __nv_bfloat16 bf16;

// ---------------------------------------------------------------------------
// Scratch (device globals; no allocation allowed in kernel_launch)
// ---------------------------------------------------------------------------
__device__ float g_rs [B_ * S_];                          // softmax row sums
__device__ bf16  g_wg [3 * C_ * C_];                      // bf16(w_qkv * gamma)
__device__ bf16  g_wp [C_ * C_];                          // bf16(w_proj)
__device__ bf16  g_xnt[(size_t)B_ * S_ * C_];             // [b][s][c] normed x
__device__ bf16  g_qkt[(size_t)B_ * S_ * 2 * C_];         // [b][s][q|k]
__device__ bf16  g_v  [(size_t)B_ * C_ * S_];             // [b][c][s]
__device__ bf16  g_P  [(size_t)B_ * S_ * S_];             // [b][i][j] exp-scores
__device__ bf16  g_Ot [(size_t)B_ * S_ * C_];             // [b][s][c]

// ---------------------------------------------------------------------------
// PTX helpers (baseline ISA only)
// ---------------------------------------------------------------------------
#define CP_ASYNC16(dst, src) \
    asm volatile("cp.async.cg.shared.global [%0], [%1], 16;" :: "r"(dst), "l"(src))
#define CP_COMMIT() asm volatile("cp.async.commit_group;" ::: "memory")
#define CP_WAIT(n)  asm volatile("cp.async.wait_group %0;" :: "n"(n) : "memory")

__device__ __forceinline__ void ldsm4(uint32_t& r0, uint32_t& r1, uint32_t& r2,
                                      uint32_t& r3, uint32_t addr) {
    asm volatile("ldmatrix.sync.aligned.m8n8.x4.shared.b16 {%0,%1,%2,%3}, [%4];"
                 : "=r"(r0), "=r"(r1), "=r"(r2), "=r"(r3) : "r"(addr));
}

__device__ __forceinline__ void mma16(float* c, const uint32_t* a, const uint32_t* b) {
    asm volatile(
        "mma.sync.aligned.m16n8k16.row.col.f32.bf16.bf16.f32 "
        "{%0,%1,%2,%3}, {%4,%5,%6,%7}, {%8,%9}, {%0,%1,%2,%3};"
        : "+f"(c[0]), "+f"(c[1]), "+f"(c[2]), "+f"(c[3])
        : "r"(a[0]), "r"(a[1]), "r"(a[2]), "r"(a[3]), "r"(b[0]), "r"(b[1]));
}

// ---------------------------------------------------------------------------
// Prep kernels
// ---------------------------------------------------------------------------
// merged weight convert: i < 3*C*C -> wg, i < C*C also converts wp
__global__ void wcvt_kernel(bf16* __restrict__ wg, bf16* __restrict__ wp,
                            const float* __restrict__ wq, const float* __restrict__ g,
                            const float* __restrict__ wpr) {
    int i = blockIdx.x * 256 + threadIdx.x;
    if (i < 3 * C_ * C_) wg[i] = __float2bfloat16_rn(wq[i] * g[i % C_]);
    if (i < C_ * C_)     wp[i] = __float2bfloat16_rn(wpr[i]);
}

__global__ void zero_rs(float* __restrict__ rs) {
    rs[blockIdx.x * 256 + threadIdx.x] = 0.f;
}

// fused rms-norm + transpose: one pass over x.
// block (32 s, 8 c-slices); stages 32 x 384 fp32 tile in smem, computes the
// per-pixel scale in-block, writes xnt[b][s][c] = bf16(x[b][c][s] * scale).
__global__ void norm_kernel(bf16* __restrict__ xnt, const float* __restrict__ x) {
    extern __shared__ float t[];                 // [384][33]
    __shared__ float red[8][32];
    __shared__ float sscl[32];
    const int tx = threadIdx.x, ty = threadIdx.y;
    const int tid = ty * 32 + tx;
    const int s0 = blockIdx.x * 32;
    const int b  = blockIdx.y;
    const float* xb = x + (size_t)b * C_ * S_ + s0 + tx;

    float acc = 0.f;
#pragma unroll
    for (int i = 0; i < 48; ++i) {
        const int c = ty + i * 8;
        float v = xb[(size_t)c * S_];
        t[c * 33 + tx] = v;
        acc += v * v;
    }
    red[ty][tx] = acc;
    __syncthreads();
    if (ty == 0) {
        float u = red[0][tx];
#pragma unroll
        for (int j = 1; j < 8; ++j) u += red[j][tx];
        float l2 = sqrtf(u);
        sscl[tx] = 19.595917942265423f / fmaxf(l2, 1e-12f);  // sqrt(384)/max(l2,eps)
    }
    __syncthreads();

    bf16* o = xnt + (size_t)b * S_ * C_ + (size_t)s0 * C_;
#pragma unroll
    for (int i = 0; i < 48; ++i) {
        const int idx = i * 256 + tid;           // over 32*384 outputs [s][c]
        const int s = idx / C_;
        const int c = idx - s * C_;
        o[idx] = __float2bfloat16_rn(t[c * 33 + s] * sscl[s]);
    }
}

// ---------------------------------------------------------------------------
// Warp-MMA bf16 GEMM: D[m][n] = sum_k A[m][k]*B[n][k]
// 128x128 block tile, 8 warps (4M x 2N, warp tile 32x64), Kc=32 (2 k16 steps),
// 4-stage cp.async pipeline, ldmatrix operand fetch, fp32 accumulate.
//   EPI 0: +e2[n]  -> bf16   (qk bias)
//   EPI 1: +e2[m]  -> bf16   (v bias)
//   EPI 2: exp(acc/sqrt(C)) -> bf16, atomicAdd row sums into e3 (scores)
//   EPI 3: * 1/e3[row] -> bf16  (AV normalize by softmax row sum)
//   EPI 4: +e2[m] + e3[m*ldc+n] -> fp32 (proj bias + residual)
// All M,N multiples of 128; K multiple of 32.
// ---------------------------------------------------------------------------
#define SRB    80                    // bytes per smem row (64 data + 16 pad)
#define ATILEB (128 * SRB)           // 10240 B per operand tile
#define STGB   (2 * ATILEB)          // 20480 B per stage
#define NSTG   4

template <int EPI>
__global__ __launch_bounds__(256)
void mma_gemm(const bf16* __restrict__ Ag, const bf16* __restrict__ Bg,
              void* __restrict__ Cgv, int K, int lda, int ldb, int ldc,
              size_t sA, size_t sB, size_t sC,
              const float* __restrict__ e2, const float* __restrict__ e3,
              size_t e3s)
{
    extern __shared__ __align__(16) char smem[];   // NSTG * STGB bytes

    const int tid  = threadIdx.x;
    const int lane = tid & 31, wid = tid >> 5;
    const int warpM = wid & 3, warpN = wid >> 2;
    const int bz = blockIdx.z;
    const int m0 = blockIdx.y * 128, n0 = blockIdx.x * 128;

    const bf16* A  = Ag + (size_t)bz * sA + (size_t)m0 * lda;
    const bf16* Bp = Bg + (size_t)bz * sB + (size_t)n0 * ldb;
    const uint32_t smB = (uint32_t)__cvta_generic_to_shared(smem);

    // global->smem loader: thread covers rows lr and lr+64, 16B at k-halfs lq
    const int lr = tid >> 2;
    const int lq = (tid & 3) * 8;                    // halfs
    const uint32_t lqB = (uint32_t)(tid & 3) * 16;   // bytes

    // ldmatrix per-thread source offsets (bytes within a stage)
    const int g = lane >> 3, r = lane & 7;
    const uint32_t aOff = (uint32_t)((warpM * 32 + (g & 1) * 8 + r) * SRB + (g >> 1) * 16);
    const uint32_t bOff = (uint32_t)(ATILEB + (warpN * 64 + (g & 1) * 8 + r) * SRB + (g >> 1) * 16);

    float acc[2][8][4];
#pragma unroll
    for (int mf = 0; mf < 2; ++mf)
#pragma unroll
        for (int nf = 0; nf < 8; ++nf)
#pragma unroll
            for (int i = 0; i < 4; ++i) acc[mf][nf][i] = 0.f;

    const int nK = K >> 5;   // Kc = 32

    auto LOAD = [&](int s) {
        const int p = s & (NSTG - 1);
        const bf16* As = A  + (size_t)lr * lda + s * 32 + lq;
        const bf16* Bs = Bp + (size_t)lr * ldb + s * 32 + lq;
        uint32_t dA = smB + (uint32_t)(p * STGB + lr * SRB) + lqB;
        uint32_t dB = dA + (uint32_t)ATILEB;
        CP_ASYNC16(dA,                As);
        CP_ASYNC16(dA + 64 * SRB,     As + (size_t)64 * lda);
        CP_ASYNC16(dB,                Bs);
        CP_ASYNC16(dB + 64 * SRB,     Bs + (size_t)64 * ldb);
    };

    LOAD(0); CP_COMMIT();
    LOAD(1); CP_COMMIT();
    LOAD(2); CP_COMMIT();

    for (int s = 0; s < nK; ++s) {
        CP_WAIT(2);              // stage s landed
        __syncthreads();         // visibility + buffer-reuse fence
        if (s + 3 < nK) LOAD(s + 3);
        CP_COMMIT();             // empty group at tail keeps counts uniform

        const uint32_t pb = smB + (uint32_t)((s & (NSTG - 1)) * STGB);
#pragma unroll
        for (int kk = 0; kk < 2; ++kk) {      // two k16 steps per stage
            uint32_t afr[2][4], bfr[8][2];
#pragma unroll
            for (int mf = 0; mf < 2; ++mf)
                ldsm4(afr[mf][0], afr[mf][1], afr[mf][2], afr[mf][3],
                      pb + aOff + (uint32_t)(mf * 16 * SRB + kk * 32));
#pragma unroll
            for (int pr = 0; pr < 4; ++pr)
                ldsm4(bfr[2 * pr][0], bfr[2 * pr + 1][0],
                      bfr[2 * pr][1], bfr[2 * pr + 1][1],
                      pb + bOff + (uint32_t)(pr * 16 * SRB + kk * 32));
#pragma unroll
            for (int mf = 0; mf < 2; ++mf)
#pragma unroll
                for (int nf = 0; nf < 8; ++nf)
                    mma16(acc[mf][nf], afr[mf], bfr[nf]);
        }
    }

    // ---- epilogue ----
    const int rBase = m0 + warpM * 32 + (lane >> 2);
    const int cBase = n0 + warpN * 64 + (lane & 3) * 2;
#pragma unroll
    for (int mf = 0; mf < 2; ++mf) {
#pragma unroll
        for (int h = 0; h < 2; ++h) {
            const int row = rBase + mf * 16 + h * 8;
            float bm = 0.f;
            if (EPI == 1 || EPI == 4) bm = e2[row];
            float inv = 1.f;
            if (EPI == 3) inv = 1.f / e3[(size_t)bz * e3s + row];
            float rsum = 0.f;
#pragma unroll
            for (int nf = 0; nf < 8; ++nf) {
                const int col = cBase + nf * 8;
                float u0 = acc[mf][nf][2 * h];
                float u1 = acc[mf][nf][2 * h + 1];
                float2 o;
                if (EPI == 0) {
                    float2 bn = *(const float2*)(e2 + col);
                    o.x = u0 + bn.x; o.y = u1 + bn.y;
                } else if (EPI == 1) {
                    o.x = u0 + bm; o.y = u1 + bm;
                } else if (EPI == 2) {
                    const float sc = 0.05103103630798288f;   // 1/sqrt(384)
                    o.x = __expf(u0 * sc); o.y = __expf(u1 * sc);
                    rsum += o.x + o.y;
                } else if (EPI == 3) {
                    o.x = u0 * inv; o.y = u1 * inv;
                } else {
                    const float* e3row = e3 + (size_t)bz * e3s + (size_t)row * ldc;
                    float2 rx = *(const float2*)(e3row + col);
                    o.x = u0 + bm + rx.x; o.y = u1 + bm + rx.y;
                }
                if (EPI == 4) {
                    float* Crow = (float*)Cgv + (size_t)bz * sC + (size_t)row * ldc;
                    *(float2*)(Crow + col) = o;
                } else {
                    bf16* Crow = (bf16*)Cgv + (size_t)bz * sC + (size_t)row * ldc;
                    __nv_bfloat162 hv = __floats2bfloat162_rn(o.x, o.y);
                    *(__nv_bfloat162*)(Crow + col) = hv;
                }
            }
            if (EPI == 2) {
                // reduce the 4 lanes sharing this row (lane^1, lane^2 keep lane>>2)
                rsum += __shfl_xor_sync(0xffffffffu, rsum, 1);
                rsum += __shfl_xor_sync(0xffffffffu, rsum, 2);
                if ((lane & 3) == 0)
                    atomicAdd((float*)(e3 + (size_t)bz * e3s + row), rsum);
            }
        }
    }
}

// ---------------------------------------------------------------------------
// Launch
// ---------------------------------------------------------------------------
extern "C" void kernel_launch(void* const* d_in, const int* in_sizes, int n_in,
                              void* d_out, int out_size) {
    const float* x      = (const float*)d_in[0];   // [4,384,64,64]
    const float* gamma  = (const float*)d_in[1];   // [384]
    const float* w_qkv  = (const float*)d_in[2];   // [1152,384]
    const float* b_qkv  = (const float*)d_in[3];   // [1152]
    const float* w_proj = (const float*)d_in[4];   // [384,384]
    const float* b_proj = (const float*)d_in[5];   // [384]
    float* out = (float*)d_out;                    // [4,384,64,64]

    float *rs;
    bf16 *wg, *wp, *xnt, *qkt, *v, *P, *Ot;
    cudaGetSymbolAddress((void**)&rs,  g_rs);
    cudaGetSymbolAddress((void**)&wg,  g_wg);
    cudaGetSymbolAddress((void**)&wp,  g_wp);
    cudaGetSymbolAddress((void**)&xnt, g_xnt);
    cudaGetSymbolAddress((void**)&qkt, g_qkt);
    cudaGetSymbolAddress((void**)&v,   g_v);
    cudaGetSymbolAddress((void**)&P,   g_P);
    cudaGetSymbolAddress((void**)&Ot,  g_Ot);

    const int SMEM_DYN = NSTG * STGB;   // 81920 bytes
    cudaFuncSetAttribute((const void*)mma_gemm<0>, cudaFuncAttributeMaxDynamicSharedMemorySize, SMEM_DYN);
    cudaFuncSetAttribute((const void*)mma_gemm<1>, cudaFuncAttributeMaxDynamicSharedMemorySize, SMEM_DYN);
    cudaFuncSetAttribute((const void*)mma_gemm<2>, cudaFuncAttributeMaxDynamicSharedMemorySize, SMEM_DYN);
    cudaFuncSetAttribute((const void*)mma_gemm<3>, cudaFuncAttributeMaxDynamicSharedMemorySize, SMEM_DYN);
    cudaFuncSetAttribute((const void*)mma_gemm<4>, cudaFuncAttributeMaxDynamicSharedMemorySize, SMEM_DYN);
    const int NORM_SMEM = C_ * 33 * 4;  // 50688 bytes
    cudaFuncSetAttribute((const void*)norm_kernel, cudaFuncAttributeMaxDynamicSharedMemorySize, NORM_SMEM);

    // 1) weight converts (one launch) + zero row sums
    wcvt_kernel<<<(3 * C_ * C_ + 255) / 256, 256>>>(wg, wp, w_qkv, gamma, w_proj);
    zero_rs<<<B_ * S_ / 256, 256>>>(rs);
    // 2) fused rms-norm + transpose: xnt[b][s][c] (single pass over x)
    norm_kernel<<<dim3(S_ / 32, B_), dim3(32, 8), NORM_SMEM>>>(xnt, x);
    // 3) qk_t[b][s][o] = xnt @ wg[0:768]^T + b_qkv[o]      M=4096 N=768 K=384
    mma_gemm<0><<<dim3(6, 32, B_), 256, SMEM_DYN>>>(
        xnt, wg, qkt, C_, C_, C_, 2 * C_,
        (size_t)S_ * C_, 0, (size_t)S_ * 2 * C_, b_qkv, nullptr, 0);
    // 4) v[b][c][s] = wg[768:] @ xnt^T + b_qkv[768+c]      M=384 N=4096 K=384
    mma_gemm<1><<<dim3(32, 3, B_), 256, SMEM_DYN>>>(
        wg + (size_t)2 * C_ * C_, xnt, v, C_, C_, C_, S_,
        0, (size_t)S_ * C_, (size_t)C_ * S_, b_qkv + 2 * C_, nullptr, 0);
    // 5) P[b][i][j] = exp(q_i . k_j / sqrt(C)); rs[b][i] += row sums
    mma_gemm<2><<<dim3(32, 32, B_), 256, SMEM_DYN>>>(
        qkt, qkt + C_, P, C_, 2 * C_, 2 * C_, S_,
        (size_t)S_ * 2 * C_, (size_t)S_ * 2 * C_, (size_t)S_ * S_,
        nullptr, rs, S_);
    // 6) Ot[b][i][c] = (P @ v^T) / rs[b][i]                M=4096 N=384 K=4096
    mma_gemm<3><<<dim3(3, 32, B_), 256, SMEM_DYN>>>(
        P, v, Ot, S_, S_, S_, C_,
        (size_t)S_ * S_, (size_t)C_ * S_, (size_t)S_ * C_,
        nullptr, rs, S_);
    // 7) out[b][o][s] = Wp @ Ot^T + b_proj[o] + x          M=384 N=4096 K=384
    mma_gemm<4><<<dim3(32, 3, B_), 256, SMEM_DYN>>>(
        wp, Ot, out, C_, C_, C_, S_,
        0, (size_t)S_ * C_, (size_t)C_ * S_, b_proj, x, (size_t)C_ * S_);
}

// round 16
// speedup vs baseline: 1.2875x; 1.0170x over previous
#include <cuda_runtime.h>
#include <cuda_bf16.h>
#include <cstdint>
#include <cstddef>

// Problem constants
#define B_   4
#define C_   384
#define S_   4096

typedef __nv_bfloat16 bf16;

// ---------------------------------------------------------------------------
// Scratch (device globals; no allocation allowed in kernel_launch)
// ---------------------------------------------------------------------------
__device__ float g_rs [B_ * S_];                          // softmax row sums
__device__ bf16  g_wg [3 * C_ * C_];                      // bf16(w_qkv * gamma)
__device__ bf16  g_wp [C_ * C_];                          // bf16(w_proj)
__device__ bf16  g_xnt[(size_t)B_ * S_ * C_];             // [b][s][c] normed x
__device__ bf16  g_qkt[(size_t)B_ * S_ * 2 * C_];         // [b][s][q|k]
__device__ bf16  g_v  [(size_t)B_ * C_ * S_];             // [b][c][s]
__device__ bf16  g_P  [(size_t)B_ * S_ * S_];             // [b][i][j] exp-scores
__device__ bf16  g_Ot [(size_t)B_ * S_ * C_];             // [b][s][c]

// ---------------------------------------------------------------------------
// PTX helpers (baseline ISA only)
// ---------------------------------------------------------------------------
#define CP_ASYNC16(dst, src) \
    asm volatile("cp.async.cg.shared.global [%0], [%1], 16;" :: "r"(dst), "l"(src))
#define CP_COMMIT() asm volatile("cp.async.commit_group;" ::: "memory")
#define CP_WAIT(n)  asm volatile("cp.async.wait_group %0;" :: "n"(n) : "memory")

__device__ __forceinline__ void ldsm4(uint32_t& r0, uint32_t& r1, uint32_t& r2,
                                      uint32_t& r3, uint32_t addr) {
    asm volatile("ldmatrix.sync.aligned.m8n8.x4.shared.b16 {%0,%1,%2,%3}, [%4];"
                 : "=r"(r0), "=r"(r1), "=r"(r2), "=r"(r3) : "r"(addr));
}

__device__ __forceinline__ void mma16(float* c, const uint32_t* a, const uint32_t* b) {
    asm volatile(
        "mma.sync.aligned.m16n8k16.row.col.f32.bf16.bf16.f32 "
        "{%0,%1,%2,%3}, {%4,%5,%6,%7}, {%8,%9}, {%0,%1,%2,%3};"
        : "+f"(c[0]), "+f"(c[1]), "+f"(c[2]), "+f"(c[3])
        : "r"(a[0]), "r"(a[1]), "r"(a[2]), "r"(a[3]), "r"(b[0]), "r"(b[1]));
}

// ---------------------------------------------------------------------------
// Prep kernels
// ---------------------------------------------------------------------------
// merged weight convert + rs zeroing
__global__ void wcvt_kernel(bf16* __restrict__ wg, bf16* __restrict__ wp,
                            const float* __restrict__ wq, const float* __restrict__ g,
                            const float* __restrict__ wpr, float* __restrict__ rs) {
    int i = blockIdx.x * 256 + threadIdx.x;
    if (i < 3 * C_ * C_) wg[i] = __float2bfloat16_rn(wq[i] * g[i % C_]);
    if (i < C_ * C_)     wp[i] = __float2bfloat16_rn(wpr[i]);
    if (i < B_ * S_)     rs[i] = 0.f;
}

// fused rms-norm + transpose: one pass over x.
// block (32 s, 8 c-slices); stages 32 x 384 fp32 tile in smem, computes the
// per-pixel scale in-block, writes xnt[b][s][c] = bf16(x[b][c][s] * scale).
__global__ void norm_kernel(bf16* __restrict__ xnt, const float* __restrict__ x) {
    extern __shared__ float t[];                 // [384][33]
    __shared__ float red[8][32];
    __shared__ float sscl[32];
    const int tx = threadIdx.x, ty = threadIdx.y;
    const int tid = ty * 32 + tx;
    const int s0 = blockIdx.x * 32;
    const int b  = blockIdx.y;
    const float* xb = x + (size_t)b * C_ * S_ + s0 + tx;

    float acc = 0.f;
#pragma unroll
    for (int i = 0; i < 48; ++i) {
        const int c = ty + i * 8;
        float v = xb[(size_t)c * S_];
        t[c * 33 + tx] = v;
        acc += v * v;
    }
    red[ty][tx] = acc;
    __syncthreads();
    if (ty == 0) {
        float u = red[0][tx];
#pragma unroll
        for (int j = 1; j < 8; ++j) u += red[j][tx];
        float l2 = sqrtf(u);
        sscl[tx] = 19.595917942265423f / fmaxf(l2, 1e-12f);  // sqrt(384)/max(l2,eps)
    }
    __syncthreads();

    bf16* o = xnt + (size_t)b * S_ * C_ + (size_t)s0 * C_;
#pragma unroll
    for (int i = 0; i < 48; ++i) {
        const int idx = i * 256 + tid;           // over 32*384 outputs [s][c]
        const int s = idx / C_;
        const int c = idx - s * C_;
        o[idx] = __float2bfloat16_rn(t[c * 33 + s] * sscl[s]);
    }
}

// ---------------------------------------------------------------------------
// Shared GEMM tile machinery (R8-proven): 128x128 block tile, 8 warps
// (4M x 2N, warp tile 32x64), Kc=32, 4-stage cp.async pipeline.
// ---------------------------------------------------------------------------
#define SRB    80                    // bytes per smem row (64 data + 16 pad)
#define ATILEB (128 * SRB)           // 10240 B per operand tile
#define STGB   (2 * ATILEB)          // 20480 B per stage
#define NSTG   4

#define GEMM_MAINLOOP(A, Bp, lda, ldb, K)                                        \
    const uint32_t smB = (uint32_t)__cvta_generic_to_shared(smem);               \
    const int lr = tid >> 2;                                                     \
    const int lq = (tid & 3) * 8;                                                \
    const uint32_t lqB = (uint32_t)(tid & 3) * 16;                               \
    const int g = lane >> 3, r = lane & 7;                                       \
    const uint32_t aOff = (uint32_t)((warpM * 32 + (g & 1) * 8 + r) * SRB + (g >> 1) * 16); \
    const uint32_t bOff = (uint32_t)(ATILEB + (warpN * 64 + (g & 1) * 8 + r) * SRB + (g >> 1) * 16); \
    float acc[2][8][4];                                                          \
    _Pragma("unroll")                                                            \
    for (int mf = 0; mf < 2; ++mf)                                               \
        _Pragma("unroll")                                                        \
        for (int nf = 0; nf < 8; ++nf)                                           \
            _Pragma("unroll")                                                    \
            for (int i = 0; i < 4; ++i) acc[mf][nf][i] = 0.f;                    \
    const int nK = (K) >> 5;                                                     \
    auto LOAD = [&](int s) {                                                     \
        const int p = s & (NSTG - 1);                                            \
        const bf16* As = (A)  + (size_t)lr * (lda) + s * 32 + lq;                \
        const bf16* Bs = (Bp) + (size_t)lr * (ldb) + s * 32 + lq;                \
        uint32_t dA = smB + (uint32_t)(p * STGB + lr * SRB) + lqB;               \
        uint32_t dB = dA + (uint32_t)ATILEB;                                     \
        CP_ASYNC16(dA,            As);                                           \
        CP_ASYNC16(dA + 64 * SRB, As + (size_t)64 * (lda));                      \
        CP_ASYNC16(dB,            Bs);                                           \
        CP_ASYNC16(dB + 64 * SRB, Bs + (size_t)64 * (ldb));                      \
    };                                                                           \
    LOAD(0); CP_COMMIT();                                                        \
    LOAD(1); CP_COMMIT();                                                        \
    LOAD(2); CP_COMMIT();                                                        \
    for (int s = 0; s < nK; ++s) {                                               \
        CP_WAIT(2);                                                              \
        __syncthreads();                                                         \
        if (s + 3 < nK) LOAD(s + 3);                                             \
        CP_COMMIT();                                                             \
        const uint32_t pb = smB + (uint32_t)((s & (NSTG - 1)) * STGB);           \
        _Pragma("unroll")                                                        \
        for (int kk = 0; kk < 2; ++kk) {                                         \
            uint32_t afr[2][4], bfr[8][2];                                       \
            _Pragma("unroll")                                                    \
            for (int mf = 0; mf < 2; ++mf)                                       \
                ldsm4(afr[mf][0], afr[mf][1], afr[mf][2], afr[mf][3],            \
                      pb + aOff + (uint32_t)(mf * 16 * SRB + kk * 32));          \
            _Pragma("unroll")                                                    \
            for (int pr = 0; pr < 4; ++pr)                                       \
                ldsm4(bfr[2 * pr][0], bfr[2 * pr + 1][0],                        \
                      bfr[2 * pr][1], bfr[2 * pr + 1][1],                        \
                      pb + bOff + (uint32_t)(pr * 16 * SRB + kk * 32));          \
            _Pragma("unroll")                                                    \
            for (int mf = 0; mf < 2; ++mf)                                       \
                _Pragma("unroll")                                                \
                for (int nf = 0; nf < 8; ++nf)                                   \
                    mma16(acc[mf][nf], afr[mf], bfr[nf]);                        \
        }                                                                        \
    }

// ---------------------------------------------------------------------------
// Combined qkv + v GEMM (independent tiles packed into one launch).
// blockIdx.x in [0,288): t<192 -> qkv tile (6 x 32), else -> v tile (32 x 3).
//   qkv: qkt[s][o] = xnt @ wg[0:768]^T + b_qkv[o]   (col bias)
//   v:   v[c][s]   = wg[768:] @ xnt^T + b_qkv[768+c] (row bias)
// ---------------------------------------------------------------------------
__global__ __launch_bounds__(256)
void qkv_v_gemm(const bf16* __restrict__ xnt, const bf16* __restrict__ wg,
                bf16* __restrict__ qkt, bf16* __restrict__ vout,
                const float* __restrict__ bq)
{
    extern __shared__ __align__(16) char smem[];
    const int tid  = threadIdx.x;
    const int lane = tid & 31, wid = tid >> 5;
    const int warpM = wid & 3, warpN = wid >> 2;
    const int bz = blockIdx.z;
    const int t = blockIdx.x;
    const bool isQ = t < 192;

    const bf16 *A, *Bp;
    bf16* Cp;
    int ldc, m0, n0;
    const float* bias;
    if (isQ) {
        int bx = t % 6, by = t / 6;
        m0 = by * 128; n0 = bx * 128;
        A  = xnt + (size_t)bz * S_ * C_ + (size_t)m0 * C_;
        Bp = wg + (size_t)n0 * C_;
        Cp = qkt + (size_t)bz * S_ * 2 * C_;
        ldc = 2 * C_;
        bias = bq;
    } else {
        int t2 = t - 192;
        int bx = t2 % 32, by = t2 / 32;
        m0 = by * 128; n0 = bx * 128;
        A  = wg + (size_t)2 * C_ * C_ + (size_t)m0 * C_;
        Bp = xnt + (size_t)bz * S_ * C_ + (size_t)n0 * C_;
        Cp = vout + (size_t)bz * C_ * S_;
        ldc = S_;
        bias = bq + 2 * C_;
    }

    GEMM_MAINLOOP(A, Bp, C_, C_, C_)

    // epilogue
    const int rBase = m0 + warpM * 32 + (lane >> 2);
    const int cBase = n0 + warpN * 64 + (lane & 3) * 2;
#pragma unroll
    for (int mf = 0; mf < 2; ++mf) {
#pragma unroll
        for (int h = 0; h < 2; ++h) {
            const int row = rBase + mf * 16 + h * 8;
            float bm = isQ ? 0.f : bias[row];
#pragma unroll
            for (int nf = 0; nf < 8; ++nf) {
                const int col = cBase + nf * 8;
                float u0 = acc[mf][nf][2 * h];
                float u1 = acc[mf][nf][2 * h + 1];
                float2 o;
                if (isQ) {
                    float2 bn = *(const float2*)(bias + col);
                    o.x = u0 + bn.x; o.y = u1 + bn.y;
                } else {
                    o.x = u0 + bm; o.y = u1 + bm;
                }
                bf16* Crow = Cp + (size_t)row * ldc;
                __nv_bfloat162 hv = __floats2bfloat162_rn(o.x, o.y);
                *(__nv_bfloat162*)(Crow + col) = hv;
            }
        }
    }
}

// ---------------------------------------------------------------------------
// Templated GEMM for the dependency chain (scores / AV / proj).
//   EPI 2: exp(acc/sqrt(C)) -> bf16, atomicAdd row sums into e3 (scores)
//   EPI 3: * 1/e3[row] -> bf16  (AV normalize by softmax row sum)
//   EPI 4: +e2[m] + e3[m*ldc+n] -> fp32 (proj bias + residual)
// ---------------------------------------------------------------------------
template <int EPI>
__global__ __launch_bounds__(256)
void mma_gemm(const bf16* __restrict__ Ag, const bf16* __restrict__ Bg,
              void* __restrict__ Cgv, int K, int lda, int ldb, int ldc,
              size_t sA, size_t sB, size_t sC,
              const float* __restrict__ e2, const float* __restrict__ e3,
              size_t e3s)
{
    extern __shared__ __align__(16) char smem[];
    const int tid  = threadIdx.x;
    const int lane = tid & 31, wid = tid >> 5;
    const int warpM = wid & 3, warpN = wid >> 2;
    const int bz = blockIdx.z;
    const int m0 = blockIdx.y * 128, n0 = blockIdx.x * 128;

    const bf16* A  = Ag + (size_t)bz * sA + (size_t)m0 * lda;
    const bf16* Bp = Bg + (size_t)bz * sB + (size_t)n0 * ldb;

    GEMM_MAINLOOP(A, Bp, lda, ldb, K)

    // ---- epilogue ----
    const int rBase = m0 + warpM * 32 + (lane >> 2);
    const int cBase = n0 + warpN * 64 + (lane & 3) * 2;
#pragma unroll
    for (int mf = 0; mf < 2; ++mf) {
#pragma unroll
        for (int h = 0; h < 2; ++h) {
            const int row = rBase + mf * 16 + h * 8;
            float bm = 0.f;
            if (EPI == 4) bm = e2[row];
            float inv = 1.f;
            if (EPI == 3) inv = 1.f / e3[(size_t)bz * e3s + row];
            float rsum = 0.f;
#pragma unroll
            for (int nf = 0; nf < 8; ++nf) {
                const int col = cBase + nf * 8;
                float u0 = acc[mf][nf][2 * h];
                float u1 = acc[mf][nf][2 * h + 1];
                float2 o;
                if (EPI == 2) {
                    const float sc = 0.05103103630798288f;   // 1/sqrt(384)
                    o.x = __expf(u0 * sc); o.y = __expf(u1 * sc);
                    rsum += o.x + o.y;
                } else if (EPI == 3) {
                    o.x = u0 * inv; o.y = u1 * inv;
                } else {
                    const float* e3row = e3 + (size_t)bz * e3s + (size_t)row * ldc;
                    float2 rx = *(const float2*)(e3row + col);
                    o.x = u0 + bm + rx.x; o.y = u1 + bm + rx.y;
                }
                if (EPI == 4) {
                    float* Crow = (float*)Cgv + (size_t)bz * sC + (size_t)row * ldc;
                    *(float2*)(Crow + col) = o;
                } else {
                    bf16* Crow = (bf16*)Cgv + (size_t)bz * sC + (size_t)row * ldc;
                    __nv_bfloat162 hv = __floats2bfloat162_rn(o.x, o.y);
                    *(__nv_bfloat162*)(Crow + col) = hv;
                }
            }
            if (EPI == 2) {
                // reduce the 4 lanes sharing this row (lane^1, lane^2 keep lane>>2)
                rsum += __shfl_xor_sync(0xffffffffu, rsum, 1);
                rsum += __shfl_xor_sync(0xffffffffu, rsum, 2);
                if ((lane & 3) == 0)
                    atomicAdd((float*)(e3 + (size_t)bz * e3s + row), rsum);
            }
        }
    }
}

// ---------------------------------------------------------------------------
// Launch
// ---------------------------------------------------------------------------
extern "C" void kernel_launch(void* const* d_in, const int* in_sizes, int n_in,
                              void* d_out, int out_size) {
    const float* x      = (const float*)d_in[0];   // [4,384,64,64]
    const float* gamma  = (const float*)d_in[1];   // [384]
    const float* w_qkv  = (const float*)d_in[2];   // [1152,384]
    const float* b_qkv  = (const float*)d_in[3];   // [1152]
    const float* w_proj = (const float*)d_in[4];   // [384,384]
    const float* b_proj = (const float*)d_in[5];   // [384]
    float* out = (float*)d_out;                    // [4,384,64,64]

    float *rs;
    bf16 *wg, *wp, *xnt, *qkt, *v, *P, *Ot;
    cudaGetSymbolAddress((void**)&rs,  g_rs);
    cudaGetSymbolAddress((void**)&wg,  g_wg);
    cudaGetSymbolAddress((void**)&wp,  g_wp);
    cudaGetSymbolAddress((void**)&xnt, g_xnt);
    cudaGetSymbolAddress((void**)&qkt, g_qkt);
    cudaGetSymbolAddress((void**)&v,   g_v);
    cudaGetSymbolAddress((void**)&P,   g_P);
    cudaGetSymbolAddress((void**)&Ot,  g_Ot);

    const int SMEM_DYN = NSTG * STGB;   // 81920 bytes
    cudaFuncSetAttribute((const void*)qkv_v_gemm, cudaFuncAttributeMaxDynamicSharedMemorySize, SMEM_DYN);
    cudaFuncSetAttribute((const void*)mma_gemm<2>, cudaFuncAttributeMaxDynamicSharedMemorySize, SMEM_DYN);
    cudaFuncSetAttribute((const void*)mma_gemm<3>, cudaFuncAttributeMaxDynamicSharedMemorySize, SMEM_DYN);
    cudaFuncSetAttribute((const void*)mma_gemm<4>, cudaFuncAttributeMaxDynamicSharedMemorySize, SMEM_DYN);
    const int NORM_SMEM = C_ * 33 * 4;  // 50688 bytes
    cudaFuncSetAttribute((const void*)norm_kernel, cudaFuncAttributeMaxDynamicSharedMemorySize, NORM_SMEM);

    // 1) weight converts + rs zeroing (one launch)
    wcvt_kernel<<<(3 * C_ * C_ + 255) / 256, 256>>>(wg, wp, w_qkv, gamma, w_proj, rs);
    // 2) fused rms-norm + transpose: xnt[b][s][c] (single pass over x)
    norm_kernel<<<dim3(S_ / 32, B_), dim3(32, 8), NORM_SMEM>>>(xnt, x);
    // 3) combined qkv + v GEMM (288 tiles/batch packed in one launch)
    qkv_v_gemm<<<dim3(288, 1, B_), 256, SMEM_DYN>>>(xnt, wg, qkt, v, b_qkv);
    // 4) P[b][i][j] = exp(q_i . k_j / sqrt(C)); rs[b][i] += row sums
    mma_gemm<2><<<dim3(32, 32, B_), 256, SMEM_DYN>>>(
        qkt, qkt + C_, P, C_, 2 * C_, 2 * C_, S_,
        (size_t)S_ * 2 * C_, (size_t)S_ * 2 * C_, (size_t)S_ * S_,
        nullptr, rs, S_);
    // 5) Ot[b][i][c] = (P @ v^T) / rs[b][i]                M=4096 N=384 K=4096
    mma_gemm<3><<<dim3(3, 32, B_), 256, SMEM_DYN>>>(
        P, v, Ot, S_, S_, S_, C_,
        (size_t)S_ * S_, (size_t)C_ * S_, (size_t)S_ * C_,
        nullptr, rs, S_);
    // 6) out[b][o][s] = Wp @ Ot^T + b_proj[o] + x          M=384 N=4096 K=384
    mma_gemm<4><<<dim3(32, 3, B_), 256, SMEM_DYN>>>(
        wp, Ot, out, C_, C_, C_, S_,
        0, (size_t)S_ * C_, (size_t)C_ * S_, b_proj, x, (size_t)C_ * S_);
}